// round 2
// baseline (speedup 1.0000x reference)
#include <cuda_runtime.h>

#define GH 224
#define GW 224
#define HW (GH*GW)
#define NB 8

// ---- scratch (device globals; no allocations allowed) ----
__device__ float4 g_q[(size_t)NB*8*HW];      // q, channel-grouped float4: [b][g=0..7][h][w]
__device__ float  g_featA[(size_t)NB*3*HW];  // ping
__device__ float  g_featB[(size_t)NB*3*HW];  // pong
__device__ float  g_f972[NB*972];            // linear output = f18 [b][3][18][18]

__device__ __forceinline__ int refl(int i) {
    return i < 0 ? -i : (i > GH-1 ? 2*(GH-1) - i : i);
}

// ---------------- linear: out[b,j] = x[b,:] . W[j,:] + bias[j] ----------------
__global__ void __launch_bounds__(256) linear_kernel(const float* __restrict__ x,
                                                     const float* __restrict__ Wm,
                                                     const float* __restrict__ bias)
{
    int warp = threadIdx.x >> 5, lane = threadIdx.x & 31;
    int idx = blockIdx.x * 8 + warp;          // 0..7775 = b*972 + j
    int b = idx / 972, j = idx - b * 972;
    const float* xr = x + b * 1000;
    const float* wr = Wm + (size_t)j * 1000;
    float acc = 0.f;
    for (int k = lane; k < 1000; k += 32) acc = fmaf(xr[k], wr[k], acc);
    #pragma unroll
    for (int o = 16; o; o >>= 1) acc += __shfl_xor_sync(0xffffffffu, acc, o);
    if (lane == 0) g_f972[idx] = acc + bias[j];
}

// ---------------- bicubic 18 -> 224 (torch align_corners=False, a=-0.75) ----------------
__device__ __forceinline__ void cubw(float t, float w[4]) {
    const float a = -0.75f;
    float d = 1.f + t;                                     // k=-1 (d in [1,2))
    w[0] = ((a*d - 5.f*a)*d + 8.f*a)*d - 4.f*a;
    w[1] = ((a+2.f)*t - (a+3.f))*t*t + 1.f;                // k=0
    d = 1.f - t;
    w[2] = ((a+2.f)*d - (a+3.f))*d*d + 1.f;                // k=1
    d = 2.f - t;
    w[3] = ((a*d - 5.f*a)*d + 8.f*a)*d - 4.f*a;            // k=2
}

__global__ void __launch_bounds__(256) bicubic_kernel()
{
    int pix = blockIdx.x * 256 + threadIdx.x;   // 0..HW-1 (HW = 196*256)
    int bc  = blockIdx.y;                       // 0..23 = b*3+c
    int h = pix / GW, w = pix - h * GW;
    float fy = (h + 0.5f) * (18.f/224.f) - 0.5f;
    float fx = (w + 0.5f) * (18.f/224.f) - 0.5f;
    float y0f = floorf(fy), x0f = floorf(fx);
    int y0 = (int)y0f, x0 = (int)x0f;
    float wy[4], wx[4];
    cubw(fy - y0f, wy);
    cubw(fx - x0f, wx);
    const float* src = g_f972 + bc * 324;       // [18][18]
    float acc = 0.f;
    #pragma unroll
    for (int ky = 0; ky < 4; ky++) {
        int yy = min(max(y0 + ky - 1, 0), 17);
        float ra = 0.f;
        #pragma unroll
        for (int kx = 0; kx < 4; kx++) {
            int xx = min(max(x0 + kx - 1, 0), 17);
            ra = fmaf(wx[kx], src[yy*18 + xx], ra);
        }
        acc = fmaf(wy[ky], ra, acc);
    }
    g_featA[(size_t)bc * HW + pix] = acc;
}

// ---------------- range_proj: q = W2 . gelu(W1 . g + b1) + b2  ----------------
__global__ void __launch_bounds__(256) qproj_kernel(const float* __restrict__ guidance,
                                                    const float* __restrict__ w1s,
                                                    const float* __restrict__ b1s,
                                                    const float* __restrict__ w2s,
                                                    const float* __restrict__ b2s,
                                                    int s)
{
    __shared__ float sw1[96], sb1[32], sw2[1024], sb2[32];
    int tid = threadIdx.x;
    if (tid < 96)  sw1[tid] = w1s[s*96 + tid];
    if (tid < 32)  sb1[tid] = b1s[s*32 + tid];
    if (tid >= 96 && tid < 128) sb2[tid-96] = b2s[s*32 + tid - 96];
    for (int i = tid; i < 1024; i += 256) sw2[i] = w2s[s*1024 + i];
    __syncthreads();

    int pix = blockIdx.x * 256 + tid;   // HW = 196*256, exact
    int b = blockIdx.y;
    const float* gb = guidance + (size_t)b * 3 * HW;
    float g0 = gb[pix], g1 = gb[HW + pix], g2 = gb[2*HW + pix];

    float hdn[32];
    #pragma unroll
    for (int k = 0; k < 32; k++) {
        float u = fmaf(sw1[3*k], g0, fmaf(sw1[3*k+1], g1, fmaf(sw1[3*k+2], g2, sb1[k])));
        hdn[k] = 0.5f * u * (1.f + erff(u * 0.70710678118654752f));  // exact GELU
    }

    float4* qb = g_q + (size_t)b * 8 * HW;
    #pragma unroll
    for (int g = 0; g < 8; g++) {
        float a0 = sb2[4*g+0], a1 = sb2[4*g+1], a2 = sb2[4*g+2], a3 = sb2[4*g+3];
        #pragma unroll
        for (int k = 0; k < 32; k++) {
            float hk = hdn[k];
            a0 = fmaf(sw2[(4*g+0)*32 + k], hk, a0);
            a1 = fmaf(sw2[(4*g+1)*32 + k], hk, a1);
            a2 = fmaf(sw2[(4*g+2)*32 + k], hk, a2);
            a3 = fmaf(sw2[(4*g+3)*32 + k], hk, a3);
        }
        float4 r; r.x = a0; r.y = a1; r.z = a2; r.w = a3;
        qb[(size_t)g * HW + pix] = r;
    }
}

// ------- fused JBU stage: scores (49 taps x 32ch) -> softmax(+spatial) -> adaptive conv -------
__global__ void __launch_bounds__(128) jbu_kernel(const float* __restrict__ fin,
                                                  float*       __restrict__ fout,
                                                  const float* __restrict__ temps,
                                                  const float* __restrict__ sigmas,
                                                  int s)
{
    int w = blockIdx.x * 32 + threadIdx.x;
    int h = blockIdx.y * 4  + threadIdx.y;
    int b = blockIdx.z;

    float t = __expf(temps[s]);
    t = fminf(fmaxf(t, 1e-4f), 1e4f);
    float sg = sigmas[s];
    float inv2s2 = 1.f / (2.f * sg * sg);

    const float4* qb = g_q + (size_t)b * 8 * HW;
    int pc = h * GW + w;

    float4 qc[8];
    #pragma unroll
    for (int g = 0; g < 8; g++) qc[g] = qb[(size_t)g * HW + pc];

    float sc[49];
    #pragma unroll
    for (int oy = -3; oy <= 3; oy++) {
        int hy = refl(h + oy);
        const float4* qr = qb + hy * GW;
        #pragma unroll
        for (int ox = -3; ox <= 3; ox++) {
            int wx = refl(w + ox);
            float acc = 0.f;
            #pragma unroll
            for (int g = 0; g < 8; g++) {
                float4 n = qr[(size_t)g * HW + wx];
                acc = fmaf(qc[g].x, n.x, acc);
                acc = fmaf(qc[g].y, n.y, acc);
                acc = fmaf(qc[g].z, n.z, acc);
                acc = fmaf(qc[g].w, n.w, acc);
            }
            float dy = oy * (1.f/3.f), dx = ox * (1.f/3.f);
            // fold log(spatial) into the logits; softmax+renorm collapse to one softmax
            sc[(oy+3)*7 + (ox+3)] = fmaf(t, acc, -(dy*dy + dx*dx) * inv2s2);
        }
    }

    float m = sc[0];
    #pragma unroll
    for (int p = 1; p < 49; p++) m = fmaxf(m, sc[p]);
    float sum = 0.f;
    #pragma unroll
    for (int p = 0; p < 49; p++) { float e = __expf(sc[p] - m); sc[p] = e; sum += e; }
    float rs = 1.f / sum;

    const float* fb = fin + (size_t)b * 3 * HW;
    float o0 = 0.f, o1 = 0.f, o2 = 0.f;
    int p = 0;
    #pragma unroll
    for (int oy = -3; oy <= 3; oy++) {
        int hy = refl(h + oy);
        const float* fr = fb + hy * GW;
        #pragma unroll
        for (int ox = -3; ox <= 3; ox++) {
            int wx = refl(w + ox);
            float kk = sc[p++];
            o0 = fmaf(kk, fr[wx],        o0);
            o1 = fmaf(kk, fr[HW + wx],   o1);
            o2 = fmaf(kk, fr[2*HW + wx], o2);
        }
    }
    size_t o = (size_t)b * 3 * HW + pc;
    fout[o]        = o0 * rs;
    fout[o + HW]   = o1 * rs;
    fout[o + 2*HW] = o2 * rs;
}

// ---------------- launch ----------------
extern "C" void kernel_launch(void* const* d_in, const int* in_sizes, int n_in,
                              void* d_out, int out_size)
{
    const float* x      = (const float*)d_in[0];
    const float* gd     = (const float*)d_in[1];
    const float* lw     = (const float*)d_in[2];
    const float* lb     = (const float*)d_in[3];
    const float* w1s    = (const float*)d_in[4];
    const float* b1s    = (const float*)d_in[5];
    const float* w2s    = (const float*)d_in[6];
    const float* b2s    = (const float*)d_in[7];
    const float* temps  = (const float*)d_in[8];
    const float* sigmas = (const float*)d_in[9];
    float* out = (float*)d_out;

    float *fA = nullptr, *fB = nullptr;
    cudaGetSymbolAddress((void**)&fA, g_featA);
    cudaGetSymbolAddress((void**)&fB, g_featB);

    linear_kernel<<<972, 256>>>(x, lw, lb);

    dim3 bgrid(HW/256, 24);
    bicubic_kernel<<<bgrid, 256>>>();

    dim3 qgrid(HW/256, NB);
    dim3 jgrid(GW/32, GH/4, NB);
    dim3 jblk(32, 4);

    float* ins[4]  = { fA, fB, fA, fB };
    float* outs[4] = { fB, fA, fB, out };
    for (int s = 0; s < 4; s++) {
        qproj_kernel<<<qgrid, 256>>>(gd, w1s, b1s, w2s, b2s, s);
        jbu_kernel<<<jgrid, jblk>>>(ins[s], outs[s], temps, sigmas, s);
    }
}

// round 4
// speedup vs baseline: 1.1716x; 1.1716x over previous
#include <cuda_runtime.h>
#include <cuda_fp16.h>

#define GH 224
#define GW 224
#define HW (GH*GW)
#define NB 8

// ---- scratch (device globals; no allocations allowed) ----
__device__ uint4  g_qh[(size_t)4*NB*4*HW];   // fp16 q: [stage][b][g=0..3][hw], 8 halves per uint4
__device__ float4 g_feat0[(size_t)NB*HW];    // ping (3 ch + pad)
__device__ float4 g_feat1[(size_t)NB*HW];    // pong
__device__ float  g_f972[NB*972];            // linear output [b][3][18][18]

__device__ __forceinline__ int refl(int i) {
    return i < 0 ? -i : (i > GH-1 ? 2*(GH-1) - i : i);
}

// ---------------- linear: out[b,j] = x[b,:] . W[j,:] + bias[j] ----------------
__global__ void __launch_bounds__(256) linear_kernel(const float* __restrict__ x,
                                                     const float* __restrict__ Wm,
                                                     const float* __restrict__ bias)
{
    int warp = threadIdx.x >> 5, lane = threadIdx.x & 31;
    int idx = blockIdx.x * 8 + warp;          // b*972 + j
    int b = idx / 972, j = idx - b * 972;
    const float* xr = x + b * 1000;
    const float* wr = Wm + (size_t)j * 1000;
    float acc = 0.f;
    for (int k = lane; k < 1000; k += 32) acc = fmaf(xr[k], wr[k], acc);
    #pragma unroll
    for (int o = 16; o; o >>= 1) acc += __shfl_xor_sync(0xffffffffu, acc, o);
    if (lane == 0) g_f972[idx] = acc + bias[j];
}

// ---------------- bicubic 18 -> 224 (torch align_corners=False, a=-0.75), 3ch packed ----------------
__device__ __forceinline__ void cubw(float t, float w[4]) {
    const float a = -0.75f;
    float d = 1.f + t;
    w[0] = ((a*d - 5.f*a)*d + 8.f*a)*d - 4.f*a;
    w[1] = ((a+2.f)*t - (a+3.f))*t*t + 1.f;
    d = 1.f - t;
    w[2] = ((a+2.f)*d - (a+3.f))*d*d + 1.f;
    d = 2.f - t;
    w[3] = ((a*d - 5.f*a)*d + 8.f*a)*d - 4.f*a;
}

__global__ void __launch_bounds__(256) bicubic_kernel()
{
    int pix = blockIdx.x * 256 + threadIdx.x;   // HW = 196*256 exact
    int b   = blockIdx.y;
    int h = pix / GW, w = pix - h * GW;
    float fy = (h + 0.5f) * (18.f/224.f) - 0.5f;
    float fx = (w + 0.5f) * (18.f/224.f) - 0.5f;
    float y0f = floorf(fy), x0f = floorf(fx);
    int y0 = (int)y0f, x0 = (int)x0f;
    float wy[4], wx[4];
    cubw(fy - y0f, wy);
    cubw(fx - x0f, wx);
    float acc[3];
    #pragma unroll
    for (int c = 0; c < 3; c++) {
        const float* src = g_f972 + (b*3 + c) * 324;
        float a = 0.f;
        #pragma unroll
        for (int ky = 0; ky < 4; ky++) {
            int yy = min(max(y0 + ky - 1, 0), 17);
            float ra = 0.f;
            #pragma unroll
            for (int kx = 0; kx < 4; kx++) {
                int xx = min(max(x0 + kx - 1, 0), 17);
                ra = fmaf(wx[kx], src[yy*18 + xx], ra);
            }
            a = fmaf(wy[ky], ra, a);
        }
        acc[c] = a;
    }
    float4 r; r.x = acc[0]; r.y = acc[1]; r.z = acc[2]; r.w = 0.f;
    g_feat0[(size_t)b * HW + pix] = r;
}

// ---------------- range_proj: q = W2 . gelu(W1 . g + b1) + b2, fp16 packed out ----------------
__global__ void __launch_bounds__(256) qproj_kernel(const float* __restrict__ guidance,
                                                    const float* __restrict__ w1s,
                                                    const float* __restrict__ b1s,
                                                    const float* __restrict__ w2s,
                                                    const float* __restrict__ b2s,
                                                    int s)
{
    __shared__ float sw1[96], sb1[32], sw2[1024], sb2[32];
    int tid = threadIdx.x;
    if (tid < 96)  sw1[tid] = w1s[s*96 + tid];
    if (tid < 32)  sb1[tid] = b1s[s*32 + tid];
    if (tid >= 96 && tid < 128) sb2[tid-96] = b2s[s*32 + tid - 96];
    for (int i = tid; i < 1024; i += 256) sw2[i] = w2s[s*1024 + i];
    __syncthreads();

    int pix = blockIdx.x * 256 + tid;
    int b = blockIdx.y;
    const float* gb = guidance + (size_t)b * 3 * HW;
    float g0 = gb[pix], g1 = gb[HW + pix], g2 = gb[2*HW + pix];

    float hdn[32];
    #pragma unroll
    for (int k = 0; k < 32; k++) {
        float u = fmaf(sw1[3*k], g0, fmaf(sw1[3*k+1], g1, fmaf(sw1[3*k+2], g2, sb1[k])));
        hdn[k] = 0.5f * u * (1.f + erff(u * 0.70710678118654752f));  // exact GELU
    }

    uint4* qb = g_qh + (size_t)(s*NB + b) * 4 * HW;
    #pragma unroll
    for (int g = 0; g < 4; g++) {
        float q[8];
        #pragma unroll
        for (int j = 0; j < 8; j++) {
            int row = 8*g + j;
            float a = sb2[row];
            #pragma unroll
            for (int k = 0; k < 32; k++) a = fmaf(sw2[row*32 + k], hdn[k], a);
            q[j] = a;
        }
        uint4 r;
        *reinterpret_cast<__half2*>(&r.x) = __floats2half2_rn(q[0], q[1]);
        *reinterpret_cast<__half2*>(&r.y) = __floats2half2_rn(q[2], q[3]);
        *reinterpret_cast<__half2*>(&r.z) = __floats2half2_rn(q[4], q[5]);
        *reinterpret_cast<__half2*>(&r.w) = __floats2half2_rn(q[6], q[7]);
        qb[(size_t)g * HW + pix] = r;
    }
}

// ------- fused JBU stage: scores (49 taps x 32ch fp16) -> softmax(+spatial) -> adaptive conv -------
__global__ void __launch_bounds__(128, 4) jbu_kernel(const float4* __restrict__ fin,
                                                     float4*       __restrict__ fout4,
                                                     float*        __restrict__ foutP,
                                                     const float* __restrict__ temps,
                                                     const float* __restrict__ sigmas,
                                                     int s)
{
    int w = blockIdx.x * 32 + threadIdx.x;
    int h = blockIdx.y * 4  + threadIdx.y;
    int b = blockIdx.z;

    float t = __expf(temps[s]);
    t = fminf(fmaxf(t, 1e-4f), 1e4f);
    float sg = sigmas[s];
    float inv2s2 = 1.f / (2.f * sg * sg);

    const uint4* qb = g_qh + (size_t)(s*NB + b) * 4 * HW;
    int pc = h * GW + w;

    // center q -> fp32 registers
    float qcf[32];
    #pragma unroll
    for (int g = 0; g < 4; g++) {
        uint4 c = qb[(size_t)g * HW + pc];
        float2 f;
        f = __half22float2(*reinterpret_cast<__half2*>(&c.x)); qcf[8*g+0]=f.x; qcf[8*g+1]=f.y;
        f = __half22float2(*reinterpret_cast<__half2*>(&c.y)); qcf[8*g+2]=f.x; qcf[8*g+3]=f.y;
        f = __half22float2(*reinterpret_cast<__half2*>(&c.z)); qcf[8*g+4]=f.x; qcf[8*g+5]=f.y;
        f = __half22float2(*reinterpret_cast<__half2*>(&c.w)); qcf[8*g+6]=f.x; qcf[8*g+7]=f.y;
    }

    float sc[49];
    #pragma unroll
    for (int oy = -3; oy <= 3; oy++) {
        int hy = refl(h + oy);
        const uint4* qr = qb + hy * GW;
        #pragma unroll
        for (int ox = -3; ox <= 3; ox++) {
            int wx = refl(w + ox);
            float acc0 = 0.f, acc1 = 0.f;
            #pragma unroll
            for (int g = 0; g < 4; g++) {
                uint4 n = qr[(size_t)g * HW + wx];
                float* qc = qcf + 8*g;
                float& acc = (g < 2) ? acc0 : acc1;
                float2 a;
                a = __half22float2(*reinterpret_cast<__half2*>(&n.x));
                acc = fmaf(qc[0], a.x, fmaf(qc[1], a.y, acc));
                a = __half22float2(*reinterpret_cast<__half2*>(&n.y));
                acc = fmaf(qc[2], a.x, fmaf(qc[3], a.y, acc));
                a = __half22float2(*reinterpret_cast<__half2*>(&n.z));
                acc = fmaf(qc[4], a.x, fmaf(qc[5], a.y, acc));
                a = __half22float2(*reinterpret_cast<__half2*>(&n.w));
                acc = fmaf(qc[6], a.x, fmaf(qc[7], a.y, acc));
            }
            float dy = oy * (1.f/3.f), dx = ox * (1.f/3.f);
            // fold log(spatial) into logits; softmax+spatial+renorm collapse to one softmax
            sc[(oy+3)*7 + (ox+3)] = fmaf(t, acc0 + acc1, -(dy*dy + dx*dx) * inv2s2);
        }
    }

    float m = sc[0];
    #pragma unroll
    for (int p = 1; p < 49; p++) m = fmaxf(m, sc[p]);
    float sum = 0.f;
    #pragma unroll
    for (int p = 0; p < 49; p++) { float e = __expf(sc[p] - m); sc[p] = e; sum += e; }
    float rs = 1.f / sum;

    const float4* fb = fin + (size_t)b * HW;
    float o0 = 0.f, o1 = 0.f, o2 = 0.f;
    int p = 0;
    #pragma unroll
    for (int oy = -3; oy <= 3; oy++) {
        int hy = refl(h + oy);
        const float4* fr = fb + hy * GW;
        #pragma unroll
        for (int ox = -3; ox <= 3; ox++) {
            int wx = refl(w + ox);
            float kk = sc[p++];
            float4 v = fr[wx];
            o0 = fmaf(kk, v.x, o0);
            o1 = fmaf(kk, v.y, o1);
            o2 = fmaf(kk, v.z, o2);
        }
    }
    if (foutP) {
        size_t o = (size_t)b * 3 * HW + pc;
        foutP[o]        = o0 * rs;
        foutP[o + HW]   = o1 * rs;
        foutP[o + 2*HW] = o2 * rs;
    } else {
        float4 r; r.x = o0 * rs; r.y = o1 * rs; r.z = o2 * rs; r.w = 0.f;
        fout4[(size_t)b * HW + pc] = r;
    }
}

// ---------------- launch ----------------
extern "C" void kernel_launch(void* const* d_in, const int* in_sizes, int n_in,
                              void* d_out, int out_size)
{
    const float* x      = (const float*)d_in[0];
    const float* gd     = (const float*)d_in[1];
    const float* lw     = (const float*)d_in[2];
    const float* lb     = (const float*)d_in[3];
    const float* w1s    = (const float*)d_in[4];
    const float* b1s    = (const float*)d_in[5];
    const float* w2s    = (const float*)d_in[6];
    const float* b2s    = (const float*)d_in[7];
    const float* temps  = (const float*)d_in[8];
    const float* sigmas = (const float*)d_in[9];
    float* out = (float*)d_out;

    float4 *f0 = nullptr, *f1 = nullptr;
    cudaGetSymbolAddress((void**)&f0, g_feat0);
    cudaGetSymbolAddress((void**)&f1, g_feat1);

    // lazily create side stream + events (exists before the capture call; no device mem involved)
    static cudaStream_t sQ = nullptr;
    static cudaEvent_t evFork = nullptr, evQ[4] = {nullptr,nullptr,nullptr,nullptr};
    if (!sQ) {
        cudaStreamCreateWithFlags(&sQ, cudaStreamNonBlocking);
        cudaEventCreateWithFlags(&evFork, cudaEventDisableTiming);
        for (int s = 0; s < 4; s++) cudaEventCreateWithFlags(&evQ[s], cudaEventDisableTiming);
    }

    dim3 qgrid(HW/256, NB);
    dim3 jgrid(GW/32, GH/4, NB);
    dim3 jblk(32, 4);

    // fork: qproj chain (guidance-only dependency) runs concurrently with linear/bicubic/jbu
    cudaEventRecord(evFork, 0);
    cudaStreamWaitEvent(sQ, evFork, 0);
    for (int s = 0; s < 4; s++) {
        qproj_kernel<<<qgrid, 256, 0, sQ>>>(gd, w1s, b1s, w2s, b2s, s);
        cudaEventRecord(evQ[s], sQ);
    }

    linear_kernel<<<972, 256>>>(x, lw, lb);
    bicubic_kernel<<<dim3(HW/256, NB), 256>>>();

    float4* ins[4]  = { f0, f1, f0, f1 };
    float4* outs[4] = { f1, f0, f1, nullptr };
    for (int s = 0; s < 4; s++) {
        cudaStreamWaitEvent(0, evQ[s], 0);   // join: q[s] ready
        jbu_kernel<<<jgrid, jblk>>>(ins[s], outs[s], (s == 3) ? out : nullptr,
                                    temps, sigmas, s);
    }
}

// round 7
// speedup vs baseline: 1.2431x; 1.0610x over previous
#include <cuda_runtime.h>
#include <cuda_fp16.h>

#define GH 224
#define GW 224
#define HW (GH*GW)
#define NB 8

// ---- scratch (device globals; no allocations allowed) ----
__device__ uint4  g_qh[(size_t)4*NB*4*HW];   // fp16 q: [stage][b][g=0..3][hw], 8 halves per uint4
__device__ float4 g_feat0[(size_t)NB*HW];    // ping (3 ch + pad)
__device__ float4 g_feat1[(size_t)NB*HW];    // pong
__device__ float  g_f972[NB*972];            // linear output [b][3][18][18]

__device__ __forceinline__ int refl(int i) {
    return i < 0 ? -i : (i > GH-1 ? 2*(GH-1) - i : i);
}

// ---------------- linear: out[b,j] = x[b,:] . W[j,:] + bias[j] ----------------
__global__ void __launch_bounds__(256) linear_kernel(const float* __restrict__ x,
                                                     const float* __restrict__ Wm,
                                                     const float* __restrict__ bias)
{
    int warp = threadIdx.x >> 5, lane = threadIdx.x & 31;
    int idx = blockIdx.x * 8 + warp;          // b*972 + j
    int b = idx / 972, j = idx - b * 972;
    const float* xr = x + b * 1000;
    const float* wr = Wm + (size_t)j * 1000;
    float acc = 0.f;
    for (int k = lane; k < 1000; k += 32) acc = fmaf(xr[k], wr[k], acc);
    #pragma unroll
    for (int o = 16; o; o >>= 1) acc += __shfl_xor_sync(0xffffffffu, acc, o);
    if (lane == 0) g_f972[idx] = acc + bias[j];
}

// ---------------- bicubic 18 -> 224 (torch align_corners=False, a=-0.75), 3ch packed ----------------
__device__ __forceinline__ void cubw(float t, float w[4]) {
    const float a = -0.75f;
    float d = 1.f + t;
    w[0] = ((a*d - 5.f*a)*d + 8.f*a)*d - 4.f*a;
    w[1] = ((a+2.f)*t - (a+3.f))*t*t + 1.f;
    d = 1.f - t;
    w[2] = ((a+2.f)*d - (a+3.f))*d*d + 1.f;
    d = 2.f - t;
    w[3] = ((a*d - 5.f*a)*d + 8.f*a)*d - 4.f*a;
}

__global__ void __launch_bounds__(256) bicubic_kernel()
{
    int pix = blockIdx.x * 256 + threadIdx.x;   // HW = 196*256 exact
    int b   = blockIdx.y;
    int h = pix / GW, w = pix - h * GW;
    float fy = (h + 0.5f) * (18.f/224.f) - 0.5f;
    float fx = (w + 0.5f) * (18.f/224.f) - 0.5f;
    float y0f = floorf(fy), x0f = floorf(fx);
    int y0 = (int)y0f, x0 = (int)x0f;
    float wy[4], wx[4];
    cubw(fy - y0f, wy);
    cubw(fx - x0f, wx);
    float acc[3];
    #pragma unroll
    for (int c = 0; c < 3; c++) {
        const float* src = g_f972 + (b*3 + c) * 324;
        float a = 0.f;
        #pragma unroll
        for (int ky = 0; ky < 4; ky++) {
            int yy = min(max(y0 + ky - 1, 0), 17);
            float ra = 0.f;
            #pragma unroll
            for (int kx = 0; kx < 4; kx++) {
                int xx = min(max(x0 + kx - 1, 0), 17);
                ra = fmaf(wx[kx], src[yy*18 + xx], ra);
            }
            a = fmaf(wy[ky], ra, a);
        }
        acc[c] = a;
    }
    float4 r; r.x = acc[0]; r.y = acc[1]; r.z = acc[2]; r.w = 0.f;
    g_feat0[(size_t)b * HW + pix] = r;
}

// ---------------- range_proj: q = W2 . gelu(W1 . g + b1) + b2, fp16 packed out ----------------
__global__ void __launch_bounds__(256) qproj_kernel(const float* __restrict__ guidance,
                                                    const float* __restrict__ w1s,
                                                    const float* __restrict__ b1s,
                                                    const float* __restrict__ w2s,
                                                    const float* __restrict__ b2s,
                                                    int s)
{
    __shared__ float sw1[96], sb1[32], sb2[32];
    __shared__ __align__(16) float sw2[1024];
    int tid = threadIdx.x;
    if (tid < 96)  sw1[tid] = w1s[s*96 + tid];
    if (tid < 32)  sb1[tid] = b1s[s*32 + tid];
    if (tid >= 96 && tid < 128) sb2[tid-96] = b2s[s*32 + tid - 96];
    for (int i = tid; i < 1024; i += 256) sw2[i] = w2s[s*1024 + i];
    __syncthreads();

    int pix = blockIdx.x * 256 + tid;
    int b = blockIdx.y;
    const float* gb = guidance + (size_t)b * 3 * HW;
    float g0 = gb[pix], g1 = gb[HW + pix], g2 = gb[2*HW + pix];

    float hdn[32];
    #pragma unroll
    for (int k = 0; k < 32; k++) {
        float u = fmaf(sw1[3*k], g0, fmaf(sw1[3*k+1], g1, fmaf(sw1[3*k+2], g2, sb1[k])));
        hdn[k] = 0.5f * u * (1.f + erff(u * 0.70710678118654752f));  // exact GELU
    }

    const float4* sw2v = reinterpret_cast<const float4*>(sw2);
    uint4* qb = g_qh + (size_t)(s*NB + b) * 4 * HW;
    #pragma unroll
    for (int g = 0; g < 4; g++) {
        float q[8];
        #pragma unroll
        for (int j = 0; j < 8; j++) {
            int row = 8*g + j;
            float a = sb2[row];
            #pragma unroll
            for (int kk = 0; kk < 8; kk++) {        // LDS.128 weight reads
                float4 wv = sw2v[row*8 + kk];
                a = fmaf(wv.x, hdn[4*kk+0], a);
                a = fmaf(wv.y, hdn[4*kk+1], a);
                a = fmaf(wv.z, hdn[4*kk+2], a);
                a = fmaf(wv.w, hdn[4*kk+3], a);
            }
            q[j] = a;
        }
        uint4 r;
        *reinterpret_cast<__half2*>(&r.x) = __floats2half2_rn(q[0], q[1]);
        *reinterpret_cast<__half2*>(&r.y) = __floats2half2_rn(q[2], q[3]);
        *reinterpret_cast<__half2*>(&r.z) = __floats2half2_rn(q[4], q[5]);
        *reinterpret_cast<__half2*>(&r.w) = __floats2half2_rn(q[6], q[7]);
        qb[(size_t)g * HW + pix] = r;
    }
}

// ------- fused JBU stage: scores (49 taps x 32ch fp16, hfma2) -> softmax(+spatial) -> adaptive conv -------
__global__ void __launch_bounds__(128, 4) jbu_kernel(const float4* __restrict__ fin,
                                                     float4*       __restrict__ fout4,
                                                     float*        __restrict__ foutP,
                                                     const float* __restrict__ temps,
                                                     const float* __restrict__ sigmas,
                                                     int s)
{
    int w = blockIdx.x * 32 + threadIdx.x;
    int h = blockIdx.y * 4  + threadIdx.y;
    int b = blockIdx.z;

    float t = __expf(temps[s]);
    t = fminf(fmaxf(t, 1e-4f), 1e4f);
    float sg = sigmas[s];
    float inv2s2 = 1.f / (2.f * sg * sg);

    const uint4* qb = g_qh + (size_t)(s*NB + b) * 4 * HW;
    int pc = h * GW + w;

    // center q stays packed fp16
    __half2 qc2[16];
    #pragma unroll
    for (int g = 0; g < 4; g++) {
        uint4 c = qb[(size_t)g * HW + pc];
        qc2[4*g+0] = *reinterpret_cast<__half2*>(&c.x);
        qc2[4*g+1] = *reinterpret_cast<__half2*>(&c.y);
        qc2[4*g+2] = *reinterpret_cast<__half2*>(&c.z);
        qc2[4*g+3] = *reinterpret_cast<__half2*>(&c.w);
    }

    const __half2 hz = __float2half2_rn(0.f);
    float sc[49];
    #pragma unroll
    for (int oy = -3; oy <= 3; oy++) {
        int hy = refl(h + oy);
        const uint4* qr = qb + hy * GW;
        #pragma unroll
        for (int ox = -3; ox <= 3; ox++) {
            int wx = refl(w + ox);
            __half2 a0 = hz, a1 = hz;          // two parallel fp16 accumulators
            #pragma unroll
            for (int g = 0; g < 4; g++) {
                uint4 n = qr[(size_t)g * HW + wx];
                a0 = __hfma2(qc2[4*g+0], *reinterpret_cast<__half2*>(&n.x), a0);
                a1 = __hfma2(qc2[4*g+1], *reinterpret_cast<__half2*>(&n.y), a1);
                a0 = __hfma2(qc2[4*g+2], *reinterpret_cast<__half2*>(&n.z), a0);
                a1 = __hfma2(qc2[4*g+3], *reinterpret_cast<__half2*>(&n.w), a1);
            }
            float2 f = __half22float2(__hadd2(a0, a1));
            float dy = oy * (1.f/3.f), dx = ox * (1.f/3.f);
            // fold log(spatial) into logits; softmax+spatial+renorm collapse to one softmax
            sc[(oy+3)*7 + (ox+3)] = fmaf(t, f.x + f.y, -(dy*dy + dx*dx) * inv2s2);
        }
    }

    float m = sc[0];
    #pragma unroll
    for (int p = 1; p < 49; p++) m = fmaxf(m, sc[p]);
    float sum = 0.f;
    #pragma unroll
    for (int p = 0; p < 49; p++) { float e = __expf(sc[p] - m); sc[p] = e; sum += e; }
    float rs = 1.f / sum;

    const float4* fb = fin + (size_t)b * HW;
    float o0 = 0.f, o1 = 0.f, o2 = 0.f;
    int p = 0;
    #pragma unroll
    for (int oy = -3; oy <= 3; oy++) {
        int hy = refl(h + oy);
        const float4* fr = fb + hy * GW;
        #pragma unroll
        for (int ox = -3; ox <= 3; ox++) {
            int wx = refl(w + ox);
            float kk = sc[p++];
            float4 v = fr[wx];
            o0 = fmaf(kk, v.x, o0);
            o1 = fmaf(kk, v.y, o1);
            o2 = fmaf(kk, v.z, o2);
        }
    }
    if (foutP) {
        size_t o = (size_t)b * 3 * HW + pc;
        foutP[o]        = o0 * rs;
        foutP[o + HW]   = o1 * rs;
        foutP[o + 2*HW] = o2 * rs;
    } else {
        float4 r; r.x = o0 * rs; r.y = o1 * rs; r.z = o2 * rs; r.w = 0.f;
        fout4[(size_t)b * HW + pc] = r;
    }
}

// ---------------- launch ----------------
extern "C" void kernel_launch(void* const* d_in, const int* in_sizes, int n_in,
                              void* d_out, int out_size)
{
    const float* x      = (const float*)d_in[0];
    const float* gd     = (const float*)d_in[1];
    const float* lw     = (const float*)d_in[2];
    const float* lb     = (const float*)d_in[3];
    const float* w1s    = (const float*)d_in[4];
    const float* b1s    = (const float*)d_in[5];
    const float* w2s    = (const float*)d_in[6];
    const float* b2s    = (const float*)d_in[7];
    const float* temps  = (const float*)d_in[8];
    const float* sigmas = (const float*)d_in[9];
    float* out = (float*)d_out;

    float4 *f0 = nullptr, *f1 = nullptr;
    cudaGetSymbolAddress((void**)&f0, g_feat0);
    cudaGetSymbolAddress((void**)&f1, g_feat1);

    // lazily create side stream + events (no device mem involved)
    static cudaStream_t sQ = nullptr;
    static cudaEvent_t evFork = nullptr, evQ[4] = {nullptr,nullptr,nullptr,nullptr};
    if (!sQ) {
        cudaStreamCreateWithFlags(&sQ, cudaStreamNonBlocking);
        cudaEventCreateWithFlags(&evFork, cudaEventDisableTiming);
        for (int s = 0; s < 4; s++) cudaEventCreateWithFlags(&evQ[s], cudaEventDisableTiming);
    }

    dim3 qgrid(HW/256, NB);
    dim3 jgrid(GW/32, GH/4, NB);
    dim3 jblk(32, 4);

    // fork: qproj chain (guidance-only dependency) runs concurrently with linear/bicubic/jbu
    cudaEventRecord(evFork, 0);
    cudaStreamWaitEvent(sQ, evFork, 0);
    for (int s = 0; s < 4; s++) {
        qproj_kernel<<<qgrid, 256, 0, sQ>>>(gd, w1s, b1s, w2s, b2s, s);
        cudaEventRecord(evQ[s], sQ);
    }

    linear_kernel<<<972, 256>>>(x, lw, lb);
    bicubic_kernel<<<dim3(HW/256, NB), 256>>>();

    float4* ins[4]  = { f0, f1, f0, f1 };
    float4* outs[4] = { f1, f0, f1, nullptr };
    for (int s = 0; s < 4; s++) {
        cudaStreamWaitEvent(0, evQ[s], 0);   // join: q[s] ready
        jbu_kernel<<<jgrid, jblk>>>(ins[s], outs[s], (s == 3) ? out : nullptr,
                                    temps, sigmas, s);
    }
}

// round 8
// speedup vs baseline: 2.1392x; 1.7209x over previous
#include <cuda_runtime.h>
#include <cuda_fp16.h>

#define GH 224
#define GW 224
#define HW (GH*GW)
#define NB 8

// ---- scratch (device globals; no allocations allowed) ----
__device__ uint4  g_qh[(size_t)4*NB*4*HW];   // fp16 q: [stage][b][g=0..3][hw], 8 halves per uint4
__device__ float4 g_feat0[(size_t)NB*HW];    // ping (3 ch + pad)
__device__ float4 g_feat1[(size_t)NB*HW];    // pong
__device__ float  g_f972[NB*972];            // linear output [b][3][18][18]

__device__ __forceinline__ int refl(int i) {
    return i < 0 ? -i : (i > GH-1 ? 2*(GH-1) - i : i);
}

// ---------------- linear: out[b,j] = x[b,:] . W[j,:] + bias[j] ----------------
__global__ void __launch_bounds__(256) linear_kernel(const float* __restrict__ x,
                                                     const float* __restrict__ Wm,
                                                     const float* __restrict__ bias)
{
    int warp = threadIdx.x >> 5, lane = threadIdx.x & 31;
    int idx = blockIdx.x * 8 + warp;          // b*972 + j
    int b = idx / 972, j = idx - b * 972;
    const float* xr = x + b * 1000;
    const float* wr = Wm + (size_t)j * 1000;
    float acc = 0.f;
    for (int k = lane; k < 1000; k += 32) acc = fmaf(xr[k], wr[k], acc);
    #pragma unroll
    for (int o = 16; o; o >>= 1) acc += __shfl_xor_sync(0xffffffffu, acc, o);
    if (lane == 0) g_f972[idx] = acc + bias[j];
}

// ---------------- bicubic 18 -> 224 (torch align_corners=False, a=-0.75), 3ch packed ----------------
__device__ __forceinline__ void cubw(float t, float w[4]) {
    const float a = -0.75f;
    float d = 1.f + t;
    w[0] = ((a*d - 5.f*a)*d + 8.f*a)*d - 4.f*a;
    w[1] = ((a+2.f)*t - (a+3.f))*t*t + 1.f;
    d = 1.f - t;
    w[2] = ((a+2.f)*d - (a+3.f))*d*d + 1.f;
    d = 2.f - t;
    w[3] = ((a*d - 5.f*a)*d + 8.f*a)*d - 4.f*a;
}

__global__ void __launch_bounds__(256) bicubic_kernel()
{
    int pix = blockIdx.x * 256 + threadIdx.x;   // HW = 196*256 exact
    int b   = blockIdx.y;
    int h = pix / GW, w = pix - h * GW;
    float fy = (h + 0.5f) * (18.f/224.f) - 0.5f;
    float fx = (w + 0.5f) * (18.f/224.f) - 0.5f;
    float y0f = floorf(fy), x0f = floorf(fx);
    int y0 = (int)y0f, x0 = (int)x0f;
    float wy[4], wx[4];
    cubw(fy - y0f, wy);
    cubw(fx - x0f, wx);
    float acc[3];
    #pragma unroll
    for (int c = 0; c < 3; c++) {
        const float* src = g_f972 + (b*3 + c) * 324;
        float a = 0.f;
        #pragma unroll
        for (int ky = 0; ky < 4; ky++) {
            int yy = min(max(y0 + ky - 1, 0), 17);
            float ra = 0.f;
            #pragma unroll
            for (int kx = 0; kx < 4; kx++) {
                int xx = min(max(x0 + kx - 1, 0), 17);
                ra = fmaf(wx[kx], src[yy*18 + xx], ra);
            }
            a = fmaf(wy[ky], ra, a);
        }
        acc[c] = a;
    }
    float4 r; r.x = acc[0]; r.y = acc[1]; r.z = acc[2]; r.w = 0.f;
    g_feat0[(size_t)b * HW + pix] = r;
}

// ---------------- range_proj: q = W2 . gelu(W1 . g + b1) + b2, half2 GEMV, fp16 out ----------------
__global__ void __launch_bounds__(256) qproj_kernel(const float* __restrict__ guidance,
                                                    const float* __restrict__ w1s,
                                                    const float* __restrict__ b1s,
                                                    const float* __restrict__ w2s,
                                                    const float* __restrict__ b2s,
                                                    int s)
{
    __shared__ float sw1[96], sb1[32], sb2[32];
    __shared__ __align__(16) __half2 sw2h[512];   // [row 0..31][k2 0..15]
    int tid = threadIdx.x;
    if (tid < 96)  sw1[tid] = w1s[s*96 + tid];
    if (tid < 32)  sb1[tid] = b1s[s*32 + tid];
    if (tid >= 96 && tid < 128) sb2[tid-96] = b2s[s*32 + tid - 96];
    #pragma unroll
    for (int i = tid; i < 512; i += 256)
        sw2h[i] = __floats2half2_rn(w2s[s*1024 + 2*i], w2s[s*1024 + 2*i + 1]);
    __syncthreads();

    int pix = blockIdx.x * 256 + tid;
    int b = blockIdx.y;
    const float* gb = guidance + (size_t)b * 3 * HW;
    float g0 = gb[pix], g1 = gb[HW + pix], g2 = gb[2*HW + pix];

    float hdn[32];
    #pragma unroll
    for (int k = 0; k < 32; k++) {
        float u = fmaf(sw1[3*k], g0, fmaf(sw1[3*k+1], g1, fmaf(sw1[3*k+2], g2, sb1[k])));
        hdn[k] = 0.5f * u * (1.f + erff(u * 0.70710678118654752f));  // exact GELU
    }
    __half2 h2[16];
    #pragma unroll
    for (int k = 0; k < 16; k++) h2[k] = __floats2half2_rn(hdn[2*k], hdn[2*k+1]);

    uint4* qb = g_qh + (size_t)(s*NB + b) * 4 * HW;
    #pragma unroll
    for (int g = 0; g < 4; g++) {
        float q[8];
        #pragma unroll
        for (int j = 0; j < 8; j++) {
            int row = 8*g + j;
            __half2 a = __floats2half2_rn(0.f, 0.f);
            __half2 c = __floats2half2_rn(0.f, 0.f);
            #pragma unroll
            for (int k = 0; k < 16; k += 2) {           // LDS.128 pairs
                a = __hfma2(sw2h[row*16 + k],     h2[k],     a);
                c = __hfma2(sw2h[row*16 + k + 1], h2[k + 1], c);
            }
            float2 f = __half22float2(__hadd2(a, c));
            q[j] = sb2[row] + f.x + f.y;
        }
        uint4 r;
        *reinterpret_cast<__half2*>(&r.x) = __floats2half2_rn(q[0], q[1]);
        *reinterpret_cast<__half2*>(&r.y) = __floats2half2_rn(q[2], q[3]);
        *reinterpret_cast<__half2*>(&r.z) = __floats2half2_rn(q[4], q[5]);
        *reinterpret_cast<__half2*>(&r.w) = __floats2half2_rn(q[6], q[7]);
        qb[(size_t)g * HW + pix] = r;
    }
}

// ---- 32-ch fp16 dot: center (16 half2 regs) . neighbor (4 uint4) ----
__device__ __forceinline__ float qdot(const __half2* qc, const uint4& n0, const uint4& n1,
                                      const uint4& n2, const uint4& n3)
{
    const __half2* p0 = reinterpret_cast<const __half2*>(&n0);
    const __half2* p1 = reinterpret_cast<const __half2*>(&n1);
    const __half2* p2 = reinterpret_cast<const __half2*>(&n2);
    const __half2* p3 = reinterpret_cast<const __half2*>(&n3);
    __half2 a = __hmul2(qc[0], p0[0]);
    __half2 c = __hmul2(qc[1], p0[1]);
    a = __hfma2(qc[2],  p0[2], a);  c = __hfma2(qc[3],  p0[3], c);
    a = __hfma2(qc[4],  p1[0], a);  c = __hfma2(qc[5],  p1[1], c);
    a = __hfma2(qc[6],  p1[2], a);  c = __hfma2(qc[7],  p1[3], c);
    a = __hfma2(qc[8],  p2[0], a);  c = __hfma2(qc[9],  p2[1], c);
    a = __hfma2(qc[10], p2[2], a);  c = __hfma2(qc[11], p2[3], c);
    a = __hfma2(qc[12], p3[0], a);  c = __hfma2(qc[13], p3[1], c);
    a = __hfma2(qc[14], p3[2], a);  c = __hfma2(qc[15], p3[3], c);
    float2 f = __half22float2(__hadd2(a, c));
    return f.x + f.y;
}

// ------- fused JBU: 2 rows/thread, single pass, online (no-max) softmax + adaptive conv -------
__global__ void __launch_bounds__(128, 4) jbu_kernel(const float4* __restrict__ fin,
                                                     float4*       __restrict__ fout4,
                                                     float*        __restrict__ foutP,
                                                     const float* __restrict__ temps,
                                                     const float* __restrict__ sigmas,
                                                     int s)
{
    int w  = blockIdx.x * 32 + threadIdx.x;
    int h0 = (blockIdx.y * 4 + threadIdx.y) * 2;
    int b  = blockIdx.z;

    float t = __expf(temps[s]);
    t = fminf(fmaxf(t, 1e-4f), 1e4f);
    float sg = sigmas[s];
    float inv2s2 = 1.f / (2.f * sg * sg);

    const uint4*  qb = g_qh + (size_t)(s*NB + b) * 4 * HW;
    const float4* fb = fin + (size_t)b * HW;
    int pc0 = h0 * GW + w;

    // center q for both rows, packed fp16
    __half2 qc0[16], qc1[16];
    #pragma unroll
    for (int g = 0; g < 4; g++) {
        uint4 c0 = qb[(size_t)g * HW + pc0];
        uint4 c1 = qb[(size_t)g * HW + pc0 + GW];
        const __half2* a0 = reinterpret_cast<const __half2*>(&c0);
        const __half2* a1 = reinterpret_cast<const __half2*>(&c1);
        #pragma unroll
        for (int j = 0; j < 4; j++) { qc0[4*g+j] = a0[j]; qc1[4*g+j] = a1[j]; }
    }

    int wxs[7];
    #pragma unroll
    for (int ox = 0; ox < 7; ox++) wxs[ox] = refl(w + ox - 3);

    float s0 = 0.f, o00 = 0.f, o01 = 0.f, o02 = 0.f;
    float s1 = 0.f, o10 = 0.f, o11 = 0.f, o12 = 0.f;

    #pragma unroll
    for (int r = 0; r < 8; r++) {               // rows h0-3 .. h0+4 serve both centers
        int hy = refl(h0 - 3 + r);
        const uint4*  qr = qb + (size_t)hy * GW;
        const float4* fr = fb + (size_t)hy * GW;
        float dy0 = (r - 3) * (1.f/3.f);
        float dy1 = (r - 4) * (1.f/3.f);
        float sy0 = dy0 * dy0 * inv2s2;
        float sy1 = dy1 * dy1 * inv2s2;
        #pragma unroll
        for (int ox = 0; ox < 7; ox++) {
            int wx = wxs[ox];
            uint4 n0 = qr[wx];
            uint4 n1 = qr[(size_t)HW + wx];
            uint4 n2 = qr[(size_t)2*HW + wx];
            uint4 n3 = qr[(size_t)3*HW + wx];
            float4 v = fr[wx];
            float dx = (ox - 3) * (1.f/3.f);
            float sx = dx * dx * inv2s2;
            if (r < 7) {                        // center row h0, oy = r-3
                float d = qdot(qc0, n0, n1, n2, n3);
                float e = __expf(fmaf(t, d, -(sy0 + sx)));
                s0 += e;
                o00 = fmaf(e, v.x, o00);
                o01 = fmaf(e, v.y, o01);
                o02 = fmaf(e, v.z, o02);
            }
            if (r > 0) {                        // center row h0+1, oy = r-4
                float d = qdot(qc1, n0, n1, n2, n3);
                float e = __expf(fmaf(t, d, -(sy1 + sx)));
                s1 += e;
                o10 = fmaf(e, v.x, o10);
                o11 = fmaf(e, v.y, o11);
                o12 = fmaf(e, v.z, o12);
            }
        }
    }
    float r0 = 1.f / s0, r1 = 1.f / s1;

    if (foutP) {
        size_t o = (size_t)b * 3 * HW + pc0;
        foutP[o]             = o00 * r0;
        foutP[o + HW]        = o01 * r0;
        foutP[o + 2*HW]      = o02 * r0;
        foutP[o + GW]        = o10 * r1;
        foutP[o + HW + GW]   = o11 * r1;
        foutP[o + 2*HW + GW] = o12 * r1;
    } else {
        float4 a; a.x = o00 * r0; a.y = o01 * r0; a.z = o02 * r0; a.w = 0.f;
        float4 c; c.x = o10 * r1; c.y = o11 * r1; c.z = o12 * r1; c.w = 0.f;
        fout4[(size_t)b * HW + pc0]      = a;
        fout4[(size_t)b * HW + pc0 + GW] = c;
    }
}

// ---------------- launch ----------------
extern "C" void kernel_launch(void* const* d_in, const int* in_sizes, int n_in,
                              void* d_out, int out_size)
{
    const float* x      = (const float*)d_in[0];
    const float* gd     = (const float*)d_in[1];
    const float* lw     = (const float*)d_in[2];
    const float* lb     = (const float*)d_in[3];
    const float* w1s    = (const float*)d_in[4];
    const float* b1s    = (const float*)d_in[5];
    const float* w2s    = (const float*)d_in[6];
    const float* b2s    = (const float*)d_in[7];
    const float* temps  = (const float*)d_in[8];
    const float* sigmas = (const float*)d_in[9];
    float* out = (float*)d_out;

    float4 *f0 = nullptr, *f1 = nullptr;
    cudaGetSymbolAddress((void**)&f0, g_feat0);
    cudaGetSymbolAddress((void**)&f1, g_feat1);

    // lazily create side stream + events (no device mem involved)
    static cudaStream_t sQ = nullptr;
    static cudaEvent_t evFork = nullptr, evQ[4] = {nullptr,nullptr,nullptr,nullptr};
    if (!sQ) {
        cudaStreamCreateWithFlags(&sQ, cudaStreamNonBlocking);
        cudaEventCreateWithFlags(&evFork, cudaEventDisableTiming);
        for (int s = 0; s < 4; s++) cudaEventCreateWithFlags(&evQ[s], cudaEventDisableTiming);
    }

    dim3 qgrid(HW/256, NB);
    dim3 jgrid(GW/32, GH/8, NB);
    dim3 jblk(32, 4);

    // fork: qproj chain (guidance-only dependency) runs concurrently with linear/bicubic/jbu
    cudaEventRecord(evFork, 0);
    cudaStreamWaitEvent(sQ, evFork, 0);
    for (int s = 0; s < 4; s++) {
        qproj_kernel<<<qgrid, 256, 0, sQ>>>(gd, w1s, b1s, w2s, b2s, s);
        cudaEventRecord(evQ[s], sQ);
    }

    linear_kernel<<<972, 256>>>(x, lw, lb);
    bicubic_kernel<<<dim3(HW/256, NB), 256>>>();

    float4* ins[4]  = { f0, f1, f0, f1 };
    float4* outs[4] = { f1, f0, f1, nullptr };
    for (int s = 0; s < 4; s++) {
        cudaStreamWaitEvent(0, evQ[s], 0);   // join: q[s] ready
        jbu_kernel<<<jgrid, jblk>>>(ins[s], outs[s], (s == 3) ? out : nullptr,
                                    temps, sigmas, s);
    }
}

// round 9
// speedup vs baseline: 2.2622x; 1.0575x over previous
#include <cuda_runtime.h>
#include <cuda_fp16.h>

#define GH 224
#define GW 224
#define HW (GH*GW)
#define NB 8

// ---- scratch (device globals; no allocations allowed) ----
__device__ uint4  g_qh[(size_t)4*NB*4*HW];   // fp16 q: [stage][b][g=0..3][hw], 8 halves per uint4
__device__ float4 g_feat0[(size_t)NB*HW];    // ping (3 ch + pad)
__device__ float4 g_feat1[(size_t)NB*HW];    // pong
__device__ float  g_f972[NB*972];            // linear output [b][3][18][18]

__device__ __forceinline__ int refl(int i) {
    return i < 0 ? -i : (i > GH-1 ? 2*(GH-1) - i : i);
}

// ---------------- linear: out[b,j] = x[b,:] . W[j,:] + bias[j] ----------------
__global__ void __launch_bounds__(256) linear_kernel(const float* __restrict__ x,
                                                     const float* __restrict__ Wm,
                                                     const float* __restrict__ bias)
{
    int warp = threadIdx.x >> 5, lane = threadIdx.x & 31;
    int idx = blockIdx.x * 8 + warp;          // b*972 + j
    int b = idx / 972, j = idx - b * 972;
    const float* xr = x + b * 1000;
    const float* wr = Wm + (size_t)j * 1000;
    float acc = 0.f;
    for (int k = lane; k < 1000; k += 32) acc = fmaf(xr[k], wr[k], acc);
    #pragma unroll
    for (int o = 16; o; o >>= 1) acc += __shfl_xor_sync(0xffffffffu, acc, o);
    if (lane == 0) g_f972[idx] = acc + bias[j];
}

// ---------------- bicubic 18 -> 224 (torch align_corners=False, a=-0.75), 3ch packed ----------------
__device__ __forceinline__ void cubw(float t, float w[4]) {
    const float a = -0.75f;
    float d = 1.f + t;
    w[0] = ((a*d - 5.f*a)*d + 8.f*a)*d - 4.f*a;
    w[1] = ((a+2.f)*t - (a+3.f))*t*t + 1.f;
    d = 1.f - t;
    w[2] = ((a+2.f)*d - (a+3.f))*d*d + 1.f;
    d = 2.f - t;
    w[3] = ((a*d - 5.f*a)*d + 8.f*a)*d - 4.f*a;
}

__global__ void __launch_bounds__(256) bicubic_kernel()
{
    int pix = blockIdx.x * 256 + threadIdx.x;   // HW = 196*256 exact
    int b   = blockIdx.y;
    int h = pix / GW, w = pix - h * GW;
    float fy = (h + 0.5f) * (18.f/224.f) - 0.5f;
    float fx = (w + 0.5f) * (18.f/224.f) - 0.5f;
    float y0f = floorf(fy), x0f = floorf(fx);
    int y0 = (int)y0f, x0 = (int)x0f;
    float wy[4], wx[4];
    cubw(fy - y0f, wy);
    cubw(fx - x0f, wx);
    float acc[3];
    #pragma unroll
    for (int c = 0; c < 3; c++) {
        const float* src = g_f972 + (b*3 + c) * 324;
        float a = 0.f;
        #pragma unroll
        for (int ky = 0; ky < 4; ky++) {
            int yy = min(max(y0 + ky - 1, 0), 17);
            float ra = 0.f;
            #pragma unroll
            for (int kx = 0; kx < 4; kx++) {
                int xx = min(max(x0 + kx - 1, 0), 17);
                ra = fmaf(wx[kx], src[yy*18 + xx], ra);
            }
            a = fmaf(wy[ky], ra, a);
        }
        acc[c] = a;
    }
    float4 r; r.x = acc[0]; r.y = acc[1]; r.z = acc[2]; r.w = 0.f;
    g_feat0[(size_t)b * HW + pix] = r;
}

// tanh-form GELU using HW MUFU tanh (hdn abs err ~2.5e-4, below fp16-q rounding impact)
__device__ __forceinline__ float gelu_fast(float u) {
    float u2 = u * u;
    float inner = u * fmaf(0.044715f * 0.7978845608f, u2, 0.7978845608f);
    float th;
    asm("tanh.approx.f32 %0, %1;" : "=f"(th) : "f"(inner));
    return 0.5f * u * (1.f + th);
}

// ---------------- range_proj: 2 px/thread, half2 GEMV, fp16 out ----------------
__global__ void __launch_bounds__(256) qproj_kernel(const float* __restrict__ guidance,
                                                    const float* __restrict__ w1s,
                                                    const float* __restrict__ b1s,
                                                    const float* __restrict__ w2s,
                                                    const float* __restrict__ b2s,
                                                    int s)
{
    __shared__ float sw1[96], sb1[32], sb2[32];
    __shared__ __align__(16) __half2 sw2h[512];   // [row 0..31][k2 0..15]
    int tid = threadIdx.x;
    if (tid < 96)  sw1[tid] = w1s[s*96 + tid];
    if (tid < 32)  sb1[tid] = b1s[s*32 + tid];
    if (tid >= 96 && tid < 128) sb2[tid-96] = b2s[s*32 + tid - 96];
    #pragma unroll
    for (int i = tid; i < 512; i += 256)
        sw2h[i] = __floats2half2_rn(w2s[s*1024 + 2*i], w2s[s*1024 + 2*i + 1]);
    __syncthreads();

    int pixA = blockIdx.x * 512 + tid;   // thread handles pixA and pixA+256
    int pixB = pixA + 256;
    int b = blockIdx.y;
    const float* gb = guidance + (size_t)b * 3 * HW;
    float gA0 = gb[pixA], gA1 = gb[HW + pixA], gA2 = gb[2*HW + pixA];
    float gB0 = gb[pixB], gB1 = gb[HW + pixB], gB2 = gb[2*HW + pixB];

    __half2 h2a[16], h2b[16];
    #pragma unroll
    for (int k = 0; k < 16; k++) {
        float uA0 = fmaf(sw1[6*k],   gA0, fmaf(sw1[6*k+1], gA1, fmaf(sw1[6*k+2], gA2, sb1[2*k])));
        float uA1 = fmaf(sw1[6*k+3], gA0, fmaf(sw1[6*k+4], gA1, fmaf(sw1[6*k+5], gA2, sb1[2*k+1])));
        float uB0 = fmaf(sw1[6*k],   gB0, fmaf(sw1[6*k+1], gB1, fmaf(sw1[6*k+2], gB2, sb1[2*k])));
        float uB1 = fmaf(sw1[6*k+3], gB0, fmaf(sw1[6*k+4], gB1, fmaf(sw1[6*k+5], gB2, sb1[2*k+1])));
        h2a[k] = __floats2half2_rn(gelu_fast(uA0), gelu_fast(uA1));
        h2b[k] = __floats2half2_rn(gelu_fast(uB0), gelu_fast(uB1));
    }

    uint4* qb = g_qh + (size_t)(s*NB + b) * 4 * HW;
    #pragma unroll
    for (int g = 0; g < 4; g++) {
        float qA[8], qB[8];
        #pragma unroll
        for (int j = 0; j < 8; j++) {
            int row = 8*g + j;
            __half2 pa0 = __floats2half2_rn(0.f, 0.f), pa1 = pa0;
            __half2 pb0 = pa0, pb1 = pa0;
            #pragma unroll
            for (int k = 0; k < 16; k += 2) {          // weight LDS shared by both px
                __half2 w0 = sw2h[row*16 + k];
                __half2 w1 = sw2h[row*16 + k + 1];
                pa0 = __hfma2(w0, h2a[k],     pa0);
                pa1 = __hfma2(w1, h2a[k + 1], pa1);
                pb0 = __hfma2(w0, h2b[k],     pb0);
                pb1 = __hfma2(w1, h2b[k + 1], pb1);
            }
            float2 fa = __half22float2(__hadd2(pa0, pa1));
            float2 fb = __half22float2(__hadd2(pb0, pb1));
            qA[j] = sb2[row] + fa.x + fa.y;
            qB[j] = sb2[row] + fb.x + fb.y;
        }
        uint4 rA, rB;
        *reinterpret_cast<__half2*>(&rA.x) = __floats2half2_rn(qA[0], qA[1]);
        *reinterpret_cast<__half2*>(&rA.y) = __floats2half2_rn(qA[2], qA[3]);
        *reinterpret_cast<__half2*>(&rA.z) = __floats2half2_rn(qA[4], qA[5]);
        *reinterpret_cast<__half2*>(&rA.w) = __floats2half2_rn(qA[6], qA[7]);
        *reinterpret_cast<__half2*>(&rB.x) = __floats2half2_rn(qB[0], qB[1]);
        *reinterpret_cast<__half2*>(&rB.y) = __floats2half2_rn(qB[2], qB[3]);
        *reinterpret_cast<__half2*>(&rB.z) = __floats2half2_rn(qB[4], qB[5]);
        *reinterpret_cast<__half2*>(&rB.w) = __floats2half2_rn(qB[6], qB[7]);
        qb[(size_t)g * HW + pixA] = rA;
        qb[(size_t)g * HW + pixB] = rB;
    }
}

// ---- 32-ch fp16 dot: center (16 half2 regs) . neighbor (4 uint4) ----
__device__ __forceinline__ float qdot(const __half2* qc, const uint4& n0, const uint4& n1,
                                      const uint4& n2, const uint4& n3)
{
    const __half2* p0 = reinterpret_cast<const __half2*>(&n0);
    const __half2* p1 = reinterpret_cast<const __half2*>(&n1);
    const __half2* p2 = reinterpret_cast<const __half2*>(&n2);
    const __half2* p3 = reinterpret_cast<const __half2*>(&n3);
    __half2 a = __hmul2(qc[0], p0[0]);
    __half2 c = __hmul2(qc[1], p0[1]);
    a = __hfma2(qc[2],  p0[2], a);  c = __hfma2(qc[3],  p0[3], c);
    a = __hfma2(qc[4],  p1[0], a);  c = __hfma2(qc[5],  p1[1], c);
    a = __hfma2(qc[6],  p1[2], a);  c = __hfma2(qc[7],  p1[3], c);
    a = __hfma2(qc[8],  p2[0], a);  c = __hfma2(qc[9],  p2[1], c);
    a = __hfma2(qc[10], p2[2], a);  c = __hfma2(qc[11], p2[3], c);
    a = __hfma2(qc[12], p3[0], a);  c = __hfma2(qc[13], p3[1], c);
    a = __hfma2(qc[14], p3[2], a);  c = __hfma2(qc[15], p3[3], c);
    float2 f = __half22float2(__hadd2(a, c));
    return f.x + f.y;
}

// ------- fused JBU: 4 rows/thread, single pass, online (no-max) softmax + adaptive conv -------
__global__ void __launch_bounds__(128, 3) jbu_kernel(const float4* __restrict__ fin,
                                                     float4*       __restrict__ fout4,
                                                     float*        __restrict__ foutP,
                                                     const float* __restrict__ temps,
                                                     const float* __restrict__ sigmas,
                                                     int s)
{
    int w  = blockIdx.x * 32 + threadIdx.x;
    int h0 = (blockIdx.y * 4 + threadIdx.y) * 4;
    int b  = blockIdx.z;

    float t = __expf(temps[s]);
    t = fminf(fmaxf(t, 1e-4f), 1e4f);
    float sg = sigmas[s];
    float inv2s2 = 1.f / (2.f * sg * sg);

    const uint4*  qb = g_qh + (size_t)(s*NB + b) * 4 * HW;
    const float4* fb = fin + (size_t)b * HW;
    int pc0 = h0 * GW + w;

    // center q for the 4 rows, packed fp16
    __half2 qc[4][16];
    #pragma unroll
    for (int c = 0; c < 4; c++) {
        #pragma unroll
        for (int g = 0; g < 4; g++) {
            uint4 cv = qb[(size_t)g * HW + pc0 + c * GW];
            const __half2* a = reinterpret_cast<const __half2*>(&cv);
            #pragma unroll
            for (int j = 0; j < 4; j++) qc[c][4*g+j] = a[j];
        }
    }

    int wxs[7];
    #pragma unroll
    for (int ox = 0; ox < 7; ox++) wxs[ox] = refl(w + ox - 3);

    float ss[4]  = {0.f, 0.f, 0.f, 0.f};
    float oc0[4] = {0.f, 0.f, 0.f, 0.f};
    float oc1[4] = {0.f, 0.f, 0.f, 0.f};
    float oc2[4] = {0.f, 0.f, 0.f, 0.f};

    #pragma unroll
    for (int r = 0; r < 10; r++) {              // rows h0-3 .. h0+6 serve 4 centers
        int hy = refl(h0 - 3 + r);
        const uint4*  qr = qb + (size_t)hy * GW;
        const float4* fr = fb + (size_t)hy * GW;
        #pragma unroll
        for (int ox = 0; ox < 7; ox++) {
            int wx = wxs[ox];
            uint4 n0 = qr[wx];
            uint4 n1 = qr[(size_t)HW + wx];
            uint4 n2 = qr[(size_t)2*HW + wx];
            uint4 n3 = qr[(size_t)3*HW + wx];
            float4 v = fr[wx];
            float dx = (ox - 3) * (1.f/3.f);
            float sx = dx * dx * inv2s2;
            #pragma unroll
            for (int c = 0; c < 4; c++) {
                if (c <= r && r <= c + 6) {     // compile-time resolved
                    float dyv = (r - 3 - c) * (1.f/3.f);
                    float d = qdot(qc[c], n0, n1, n2, n3);
                    float e = __expf(fmaf(t, d, -fmaf(dyv, dyv * inv2s2, sx)));
                    ss[c] += e;
                    oc0[c] = fmaf(e, v.x, oc0[c]);
                    oc1[c] = fmaf(e, v.y, oc1[c]);
                    oc2[c] = fmaf(e, v.z, oc2[c]);
                }
            }
        }
    }

    if (foutP) {
        size_t o = (size_t)b * 3 * HW + pc0;
        #pragma unroll
        for (int c = 0; c < 4; c++) {
            float rs = 1.f / ss[c];
            foutP[o + c*GW]          = oc0[c] * rs;
            foutP[o + HW + c*GW]     = oc1[c] * rs;
            foutP[o + 2*HW + c*GW]   = oc2[c] * rs;
        }
    } else {
        #pragma unroll
        for (int c = 0; c < 4; c++) {
            float rs = 1.f / ss[c];
            float4 rv; rv.x = oc0[c] * rs; rv.y = oc1[c] * rs; rv.z = oc2[c] * rs; rv.w = 0.f;
            fout4[(size_t)b * HW + pc0 + c*GW] = rv;
        }
    }
}

// ---------------- launch ----------------
extern "C" void kernel_launch(void* const* d_in, const int* in_sizes, int n_in,
                              void* d_out, int out_size)
{
    const float* x      = (const float*)d_in[0];
    const float* gd     = (const float*)d_in[1];
    const float* lw     = (const float*)d_in[2];
    const float* lb     = (const float*)d_in[3];
    const float* w1s    = (const float*)d_in[4];
    const float* b1s    = (const float*)d_in[5];
    const float* w2s    = (const float*)d_in[6];
    const float* b2s    = (const float*)d_in[7];
    const float* temps  = (const float*)d_in[8];
    const float* sigmas = (const float*)d_in[9];
    float* out = (float*)d_out;

    float4 *f0 = nullptr, *f1 = nullptr;
    cudaGetSymbolAddress((void**)&f0, g_feat0);
    cudaGetSymbolAddress((void**)&f1, g_feat1);

    // lazily create side stream + events (no device mem involved)
    static cudaStream_t sQ = nullptr;
    static cudaEvent_t evFork = nullptr, evQ[4] = {nullptr,nullptr,nullptr,nullptr};
    if (!sQ) {
        cudaStreamCreateWithFlags(&sQ, cudaStreamNonBlocking);
        cudaEventCreateWithFlags(&evFork, cudaEventDisableTiming);
        for (int s = 0; s < 4; s++) cudaEventCreateWithFlags(&evQ[s], cudaEventDisableTiming);
    }

    dim3 qgrid(HW/512, NB);
    dim3 jgrid(GW/32, GH/16, NB);
    dim3 jblk(32, 4);

    // fork: qproj chain (guidance-only dependency) runs concurrently with linear/bicubic/jbu
    cudaEventRecord(evFork, 0);
    cudaStreamWaitEvent(sQ, evFork, 0);
    for (int s = 0; s < 4; s++) {
        qproj_kernel<<<qgrid, 256, 0, sQ>>>(gd, w1s, b1s, w2s, b2s, s);
        cudaEventRecord(evQ[s], sQ);
    }

    linear_kernel<<<972, 256>>>(x, lw, lb);
    bicubic_kernel<<<dim3(HW/256, NB), 256>>>();

    float4* ins[4]  = { f0, f1, f0, f1 };
    float4* outs[4] = { f1, f0, f1, nullptr };
    for (int s = 0; s < 4; s++) {
        cudaStreamWaitEvent(0, evQ[s], 0);   // join: q[s] ready
        jbu_kernel<<<jgrid, jblk>>>(ins[s], outs[s], (s == 3) ? out : nullptr,
                                    temps, sigmas, s);
    }
}

// round 14
// speedup vs baseline: 2.3347x; 1.0321x over previous
#include <cuda_runtime.h>
#include <cuda_fp16.h>

#define GH 224
#define GW 224
#define HW (GH*GW)
#define NB 8

// ---- scratch (device globals; no allocations allowed) ----
__device__ uint4  g_qh[(size_t)4*NB*4*HW];   // fp16 q: [stage][b][g=0..3][hw], 8 halves per uint4
__device__ float4 g_feat0[(size_t)NB*HW];    // ping (3 ch + pad)
__device__ float4 g_feat1[(size_t)NB*HW];    // pong
__device__ float  g_f972[NB*972];            // linear output [b][3][18][18]

__device__ __forceinline__ int refl(int i) {
    return i < 0 ? -i : (i > GH-1 ? 2*(GH-1) - i : i);
}

// ---------------- linear: out[b,j] = x[b,:] . W[j,:] + bias[j] ----------------
__global__ void __launch_bounds__(256) linear_kernel(const float* __restrict__ x,
                                                     const float* __restrict__ Wm,
                                                     const float* __restrict__ bias)
{
    int warp = threadIdx.x >> 5, lane = threadIdx.x & 31;
    int idx = blockIdx.x * 8 + warp;          // b*972 + j
    int b = idx / 972, j = idx - b * 972;
    const float* xr = x + b * 1000;
    const float* wr = Wm + (size_t)j * 1000;
    float acc = 0.f;
    for (int k = lane; k < 1000; k += 32) acc = fmaf(xr[k], wr[k], acc);
    #pragma unroll
    for (int o = 16; o; o >>= 1) acc += __shfl_xor_sync(0xffffffffu, acc, o);
    if (lane == 0) g_f972[idx] = acc + bias[j];
}

// ---------------- bicubic 18 -> 224 (torch align_corners=False, a=-0.75), 3ch packed ----------------
__device__ __forceinline__ void cubw(float t, float w[4]) {
    const float a = -0.75f;
    float d = 1.f + t;
    w[0] = ((a*d - 5.f*a)*d + 8.f*a)*d - 4.f*a;
    w[1] = ((a+2.f)*t - (a+3.f))*t*t + 1.f;
    d = 1.f - t;
    w[2] = ((a+2.f)*d - (a+3.f))*d*d + 1.f;
    d = 2.f - t;
    w[3] = ((a*d - 5.f*a)*d + 8.f*a)*d - 4.f*a;
}

__global__ void __launch_bounds__(256) bicubic_kernel()
{
    int pix = blockIdx.x * 256 + threadIdx.x;   // HW = 196*256 exact
    int b   = blockIdx.y;
    int h = pix / GW, w = pix - h * GW;
    float fy = (h + 0.5f) * (18.f/224.f) - 0.5f;
    float fx = (w + 0.5f) * (18.f/224.f) - 0.5f;
    float y0f = floorf(fy), x0f = floorf(fx);
    int y0 = (int)y0f, x0 = (int)x0f;
    float wy[4], wx[4];
    cubw(fy - y0f, wy);
    cubw(fx - x0f, wx);
    float acc[3];
    #pragma unroll
    for (int c = 0; c < 3; c++) {
        const float* src = g_f972 + (b*3 + c) * 324;
        float a = 0.f;
        #pragma unroll
        for (int ky = 0; ky < 4; ky++) {
            int yy = min(max(y0 + ky - 1, 0), 17);
            float ra = 0.f;
            #pragma unroll
            for (int kx = 0; kx < 4; kx++) {
                int xx = min(max(x0 + kx - 1, 0), 17);
                ra = fmaf(wx[kx], src[yy*18 + xx], ra);
            }
            a = fmaf(wy[ky], ra, a);
        }
        acc[c] = a;
    }
    float4 r; r.x = acc[0]; r.y = acc[1]; r.z = acc[2]; r.w = 0.f;
    g_feat0[(size_t)b * HW + pix] = r;
}

// tanh-form GELU using HW MUFU tanh (hdn abs err ~2.5e-4, below fp16-q rounding impact)
__device__ __forceinline__ float gelu_fast(float u) {
    float u2 = u * u;
    float inner = u * fmaf(0.044715f * 0.7978845608f, u2, 0.7978845608f);
    float th;
    asm("tanh.approx.f32 %0, %1;" : "=f"(th) : "f"(inner));
    return 0.5f * u * (1.f + th);
}

// ---------------- range_proj: 2 px/thread, half2 GEMV, fp16 out ----------------
__global__ void __launch_bounds__(256) qproj_kernel(const float* __restrict__ guidance,
                                                    const float* __restrict__ w1s,
                                                    const float* __restrict__ b1s,
                                                    const float* __restrict__ w2s,
                                                    const float* __restrict__ b2s,
                                                    int s)
{
    __shared__ float sw1[96], sb1[32], sb2[32];
    __shared__ __align__(16) __half2 sw2h[512];   // [row 0..31][k2 0..15]
    int tid = threadIdx.x;
    if (tid < 96)  sw1[tid] = w1s[s*96 + tid];
    if (tid < 32)  sb1[tid] = b1s[s*32 + tid];
    if (tid >= 96 && tid < 128) sb2[tid-96] = b2s[s*32 + tid - 96];
    #pragma unroll
    for (int i = tid; i < 512; i += 256)
        sw2h[i] = __floats2half2_rn(w2s[s*1024 + 2*i], w2s[s*1024 + 2*i + 1]);
    __syncthreads();

    int pixA = blockIdx.x * 512 + tid;   // thread handles pixA and pixA+256
    int pixB = pixA + 256;
    int b = blockIdx.y;
    const float* gb = guidance + (size_t)b * 3 * HW;
    float gA0 = gb[pixA], gA1 = gb[HW + pixA], gA2 = gb[2*HW + pixA];
    float gB0 = gb[pixB], gB1 = gb[HW + pixB], gB2 = gb[2*HW + pixB];

    __half2 h2a[16], h2b[16];
    #pragma unroll
    for (int k = 0; k < 16; k++) {
        float uA0 = fmaf(sw1[6*k],   gA0, fmaf(sw1[6*k+1], gA1, fmaf(sw1[6*k+2], gA2, sb1[2*k])));
        float uA1 = fmaf(sw1[6*k+3], gA0, fmaf(sw1[6*k+4], gA1, fmaf(sw1[6*k+5], gA2, sb1[2*k+1])));
        float uB0 = fmaf(sw1[6*k],   gB0, fmaf(sw1[6*k+1], gB1, fmaf(sw1[6*k+2], gB2, sb1[2*k])));
        float uB1 = fmaf(sw1[6*k+3], gB0, fmaf(sw1[6*k+4], gB1, fmaf(sw1[6*k+5], gB2, sb1[2*k+1])));
        h2a[k] = __floats2half2_rn(gelu_fast(uA0), gelu_fast(uA1));
        h2b[k] = __floats2half2_rn(gelu_fast(uB0), gelu_fast(uB1));
    }

    uint4* qb = g_qh + (size_t)(s*NB + b) * 4 * HW;
    #pragma unroll
    for (int g = 0; g < 4; g++) {
        float qA[8], qB[8];
        #pragma unroll
        for (int j = 0; j < 8; j++) {
            int row = 8*g + j;
            __half2 pa0 = __floats2half2_rn(0.f, 0.f), pa1 = pa0;
            __half2 pb0 = pa0, pb1 = pa0;
            #pragma unroll
            for (int k = 0; k < 16; k += 2) {          // weight LDS shared by both px
                __half2 w0 = sw2h[row*16 + k];
                __half2 w1 = sw2h[row*16 + k + 1];
                pa0 = __hfma2(w0, h2a[k],     pa0);
                pa1 = __hfma2(w1, h2a[k + 1], pa1);
                pb0 = __hfma2(w0, h2b[k],     pb0);
                pb1 = __hfma2(w1, h2b[k + 1], pb1);
            }
            float2 fa = __half22float2(__hadd2(pa0, pa1));
            float2 fb = __half22float2(__hadd2(pb0, pb1));
            qA[j] = sb2[row] + fa.x + fa.y;
            qB[j] = sb2[row] + fb.x + fb.y;
        }
        uint4 rA, rB;
        *reinterpret_cast<__half2*>(&rA.x) = __floats2half2_rn(qA[0], qA[1]);
        *reinterpret_cast<__half2*>(&rA.y) = __floats2half2_rn(qA[2], qA[3]);
        *reinterpret_cast<__half2*>(&rA.z) = __floats2half2_rn(qA[4], qA[5]);
        *reinterpret_cast<__half2*>(&rA.w) = __floats2half2_rn(qA[6], qA[7]);
        *reinterpret_cast<__half2*>(&rB.x) = __floats2half2_rn(qB[0], qB[1]);
        *reinterpret_cast<__half2*>(&rB.y) = __floats2half2_rn(qB[2], qB[3]);
        *reinterpret_cast<__half2*>(&rB.z) = __floats2half2_rn(qB[4], qB[5]);
        *reinterpret_cast<__half2*>(&rB.w) = __floats2half2_rn(qB[6], qB[7]);
        qb[(size_t)g * HW + pixA] = rA;
        qb[(size_t)g * HW + pixB] = rB;
    }
}

// ---- 32-ch fp16 dot: 4 independent HFMA2 chains (len 4) for ILP ----
__device__ __forceinline__ float qdot(const __half2* qc, const uint4& n0, const uint4& n1,
                                      const uint4& n2, const uint4& n3)
{
    const __half2* p0 = reinterpret_cast<const __half2*>(&n0);
    const __half2* p1 = reinterpret_cast<const __half2*>(&n1);
    const __half2* p2 = reinterpret_cast<const __half2*>(&n2);
    const __half2* p3 = reinterpret_cast<const __half2*>(&n3);
    __half2 a = __hmul2(qc[0], p0[0]);
    __half2 b = __hmul2(qc[1], p0[1]);
    __half2 c = __hmul2(qc[2], p0[2]);
    __half2 d = __hmul2(qc[3], p0[3]);
    a = __hfma2(qc[4],  p1[0], a);
    b = __hfma2(qc[5],  p1[1], b);
    c = __hfma2(qc[6],  p1[2], c);
    d = __hfma2(qc[7],  p1[3], d);
    a = __hfma2(qc[8],  p2[0], a);
    b = __hfma2(qc[9],  p2[1], b);
    c = __hfma2(qc[10], p2[2], c);
    d = __hfma2(qc[11], p2[3], d);
    a = __hfma2(qc[12], p3[0], a);
    b = __hfma2(qc[13], p3[1], b);
    c = __hfma2(qc[14], p3[2], c);
    d = __hfma2(qc[15], p3[3], d);
    float2 f = __half22float2(__hadd2(__hadd2(a, b), __hadd2(c, d)));
    return f.x + f.y;
}

// ------- fused JBU: 4 rows/thread, single pass, online (no-max) softmax + adaptive conv -------
__global__ void __launch_bounds__(128, 3) jbu_kernel(const float4* __restrict__ fin,
                                                     float4*       __restrict__ fout4,
                                                     float*        __restrict__ foutP,
                                                     const float* __restrict__ temps,
                                                     const float* __restrict__ sigmas,
                                                     int s)
{
    int w  = blockIdx.x * 32 + threadIdx.x;
    int h0 = (blockIdx.y * 4 + threadIdx.y) * 4;
    int b  = blockIdx.z;

    float t = __expf(temps[s]);
    t = fminf(fmaxf(t, 1e-4f), 1e4f);
    float sg = sigmas[s];
    float inv2s2 = 1.f / (2.f * sg * sg);

    const uint4*  qb = g_qh + (size_t)(s*NB + b) * 4 * HW;
    const float4* fb = fin + (size_t)b * HW;
    int pc0 = h0 * GW + w;

    // center q for the 4 rows, packed fp16
    __half2 qc[4][16];
    #pragma unroll
    for (int c = 0; c < 4; c++) {
        #pragma unroll
        for (int g = 0; g < 4; g++) {
            uint4 cv = qb[(size_t)g * HW + pc0 + c * GW];
            const __half2* a = reinterpret_cast<const __half2*>(&cv);
            #pragma unroll
            for (int j = 0; j < 4; j++) qc[c][4*g+j] = a[j];
        }
    }

    int wxs[7];
    #pragma unroll
    for (int ox = 0; ox < 7; ox++) wxs[ox] = refl(w + ox - 3);

    float ss[4]  = {0.f, 0.f, 0.f, 0.f};
    float oc0[4] = {0.f, 0.f, 0.f, 0.f};
    float oc1[4] = {0.f, 0.f, 0.f, 0.f};
    float oc2[4] = {0.f, 0.f, 0.f, 0.f};

    #pragma unroll
    for (int r = 0; r < 10; r++) {              // rows h0-3 .. h0+6 serve 4 centers
        int hy = refl(h0 - 3 + r);
        const uint4*  qr = qb + (size_t)hy * GW;
        const float4* fr = fb + (size_t)hy * GW;
        #pragma unroll
        for (int ox = 0; ox < 7; ox++) {
            int wx = wxs[ox];
            uint4 n0 = qr[wx];
            uint4 n1 = qr[(size_t)HW + wx];
            uint4 n2 = qr[(size_t)2*HW + wx];
            uint4 n3 = qr[(size_t)3*HW + wx];
            float4 v = fr[wx];
            float dx = (ox - 3) * (1.f/3.f);
            float sx = dx * dx * inv2s2;
            #pragma unroll
            for (int c = 0; c < 4; c++) {
                if (c <= r && r <= c + 6) {     // compile-time resolved
                    float dyv = (r - 3 - c) * (1.f/3.f);
                    float d = qdot(qc[c], n0, n1, n2, n3);
                    float e = __expf(fmaf(t, d, -fmaf(dyv, dyv * inv2s2, sx)));
                    ss[c] += e;
                    oc0[c] = fmaf(e, v.x, oc0[c]);
                    oc1[c] = fmaf(e, v.y, oc1[c]);
                    oc2[c] = fmaf(e, v.z, oc2[c]);
                }
            }
        }
    }

    if (foutP) {
        size_t o = (size_t)b * 3 * HW + pc0;
        #pragma unroll
        for (int c = 0; c < 4; c++) {
            float rs = 1.f / ss[c];
            foutP[o + c*GW]          = oc0[c] * rs;
            foutP[o + HW + c*GW]     = oc1[c] * rs;
            foutP[o + 2*HW + c*GW]   = oc2[c] * rs;
        }
    } else {
        #pragma unroll
        for (int c = 0; c < 4; c++) {
            float rs = 1.f / ss[c];
            float4 rv; rv.x = oc0[c] * rs; rv.y = oc1[c] * rs; rv.z = oc2[c] * rs; rv.w = 0.f;
            fout4[(size_t)b * HW + pc0 + c*GW] = rv;
        }
    }
}

// ---------------- launch ----------------
extern "C" void kernel_launch(void* const* d_in, const int* in_sizes, int n_in,
                              void* d_out, int out_size)
{
    const float* x      = (const float*)d_in[0];
    const float* gd     = (const float*)d_in[1];
    const float* lw     = (const float*)d_in[2];
    const float* lb     = (const float*)d_in[3];
    const float* w1s    = (const float*)d_in[4];
    const float* b1s    = (const float*)d_in[5];
    const float* w2s    = (const float*)d_in[6];
    const float* b2s    = (const float*)d_in[7];
    const float* temps  = (const float*)d_in[8];
    const float* sigmas = (const float*)d_in[9];
    float* out = (float*)d_out;

    float4 *f0 = nullptr, *f1 = nullptr;
    cudaGetSymbolAddress((void**)&f0, g_feat0);
    cudaGetSymbolAddress((void**)&f1, g_feat1);

    // lazily create side stream + events (no device mem involved)
    static cudaStream_t sQ = nullptr;
    static cudaEvent_t evFork = nullptr, evQ[4] = {nullptr,nullptr,nullptr,nullptr};
    if (!sQ) {
        cudaStreamCreateWithFlags(&sQ, cudaStreamNonBlocking);
        cudaEventCreateWithFlags(&evFork, cudaEventDisableTiming);
        for (int s = 0; s < 4; s++) cudaEventCreateWithFlags(&evQ[s], cudaEventDisableTiming);
    }

    dim3 qgrid(HW/512, NB);
    dim3 jgrid(GW/32, GH/16, NB);
    dim3 jblk(32, 4);

    float4* ins[4]  = { f0, f1, f0, f1 };
    float4* outs[4] = { f1, f0, f1, nullptr };

    // Submission order interleaves qproj/jbu so ncu (-s 5 -c 1) lands on a jbu launch.
    // Execution order is governed solely by streams + events (identical semantics).
    cudaEventRecord(evFork, 0);
    cudaStreamWaitEvent(sQ, evFork, 0);

    linear_kernel<<<972, 256>>>(x, lw, lb);                 // launch 1
    bicubic_kernel<<<dim3(HW/256, NB), 256>>>();            // launch 2
    for (int s = 0; s < 4; s++) {
        qproj_kernel<<<qgrid, 256, 0, sQ>>>(gd, w1s, b1s, w2s, b2s, s);  // launches 3,5,7,9
        cudaEventRecord(evQ[s], sQ);
        cudaStreamWaitEvent(0, evQ[s], 0);   // join: q[s] ready
        jbu_kernel<<<jgrid, jblk>>>(ins[s], outs[s], (s == 3) ? out : nullptr,
                                    temps, sigmas, s);                   // launches 4,6,8,10
    }
}

// round 16
// speedup vs baseline: 2.6192x; 1.1218x over previous
#include <cuda_runtime.h>
#include <cuda_fp16.h>

#define GH 224
#define GW 224
#define HW (GH*GW)
#define NB 8

#define TILE_W 32
#define TILE_H 8
#define HALO_W 38
#define HALO_H 14

// ---- scratch (device globals; no allocations allowed) ----
__device__ uint4  g_qh[(size_t)4*NB*4*HW];   // fp16 q: [stage][b][g=0..3][hw], 8 halves per uint4
__device__ float4 g_feat0[(size_t)NB*HW];    // ping (3 ch + pad)
__device__ float4 g_feat1[(size_t)NB*HW];    // pong
__device__ float  g_f972[NB*972];            // linear output [b][3][18][18]

__device__ __forceinline__ int refl(int i) {
    return i < 0 ? -i : (i > GH-1 ? 2*(GH-1) - i : i);
}

// ---------------- linear: out[b,j] = x[b,:] . W[j,:] + bias[j] ----------------
__global__ void __launch_bounds__(256) linear_kernel(const float* __restrict__ x,
                                                     const float* __restrict__ Wm,
                                                     const float* __restrict__ bias)
{
    int warp = threadIdx.x >> 5, lane = threadIdx.x & 31;
    int idx = blockIdx.x * 8 + warp;          // b*972 + j
    int b = idx / 972, j = idx - b * 972;
    const float* xr = x + b * 1000;
    const float* wr = Wm + (size_t)j * 1000;
    float acc = 0.f;
    for (int k = lane; k < 1000; k += 32) acc = fmaf(xr[k], wr[k], acc);
    #pragma unroll
    for (int o = 16; o; o >>= 1) acc += __shfl_xor_sync(0xffffffffu, acc, o);
    if (lane == 0) g_f972[idx] = acc + bias[j];
}

// ---------------- bicubic 18 -> 224 (torch align_corners=False, a=-0.75), 3ch packed ----------------
__device__ __forceinline__ void cubw(float t, float w[4]) {
    const float a = -0.75f;
    float d = 1.f + t;
    w[0] = ((a*d - 5.f*a)*d + 8.f*a)*d - 4.f*a;
    w[1] = ((a+2.f)*t - (a+3.f))*t*t + 1.f;
    d = 1.f - t;
    w[2] = ((a+2.f)*d - (a+3.f))*d*d + 1.f;
    d = 2.f - t;
    w[3] = ((a*d - 5.f*a)*d + 8.f*a)*d - 4.f*a;
}

__global__ void __launch_bounds__(256) bicubic_kernel()
{
    int pix = blockIdx.x * 256 + threadIdx.x;   // HW = 196*256 exact
    int b   = blockIdx.y;
    int h = pix / GW, w = pix - h * GW;
    float fy = (h + 0.5f) * (18.f/224.f) - 0.5f;
    float fx = (w + 0.5f) * (18.f/224.f) - 0.5f;
    float y0f = floorf(fy), x0f = floorf(fx);
    int y0 = (int)y0f, x0 = (int)x0f;
    float wy[4], wx[4];
    cubw(fy - y0f, wy);
    cubw(fx - x0f, wx);
    float acc[3];
    #pragma unroll
    for (int c = 0; c < 3; c++) {
        const float* src = g_f972 + (b*3 + c) * 324;
        float a = 0.f;
        #pragma unroll
        for (int ky = 0; ky < 4; ky++) {
            int yy = min(max(y0 + ky - 1, 0), 17);
            float ra = 0.f;
            #pragma unroll
            for (int kx = 0; kx < 4; kx++) {
                int xx = min(max(x0 + kx - 1, 0), 17);
                ra = fmaf(wx[kx], src[yy*18 + xx], ra);
            }
            a = fmaf(wy[ky], ra, a);
        }
        acc[c] = a;
    }
    float4 r; r.x = acc[0]; r.y = acc[1]; r.z = acc[2]; r.w = 0.f;
    g_feat0[(size_t)b * HW + pix] = r;
}

// tanh-form GELU using HW MUFU tanh (hdn abs err ~2.5e-4, below fp16-q rounding impact)
__device__ __forceinline__ float gelu_fast(float u) {
    float u2 = u * u;
    float inner = u * fmaf(0.044715f * 0.7978845608f, u2, 0.7978845608f);
    float th;
    asm("tanh.approx.f32 %0, %1;" : "=f"(th) : "f"(inner));
    return 0.5f * u * (1.f + th);
}

// ---------------- range_proj: 2 px/thread, half2 GEMV, fp16 out ----------------
__global__ void __launch_bounds__(256) qproj_kernel(const float* __restrict__ guidance,
                                                    const float* __restrict__ w1s,
                                                    const float* __restrict__ b1s,
                                                    const float* __restrict__ w2s,
                                                    const float* __restrict__ b2s,
                                                    int s)
{
    __shared__ float sw1[96], sb1[32], sb2[32];
    __shared__ __align__(16) __half2 sw2h[512];   // [row 0..31][k2 0..15]
    int tid = threadIdx.x;
    if (tid < 96)  sw1[tid] = w1s[s*96 + tid];
    if (tid < 32)  sb1[tid] = b1s[s*32 + tid];
    if (tid >= 96 && tid < 128) sb2[tid-96] = b2s[s*32 + tid - 96];
    #pragma unroll
    for (int i = tid; i < 512; i += 256)
        sw2h[i] = __floats2half2_rn(w2s[s*1024 + 2*i], w2s[s*1024 + 2*i + 1]);
    __syncthreads();

    int pixA = blockIdx.x * 512 + tid;   // thread handles pixA and pixA+256
    int pixB = pixA + 256;
    int b = blockIdx.y;
    const float* gb = guidance + (size_t)b * 3 * HW;
    float gA0 = gb[pixA], gA1 = gb[HW + pixA], gA2 = gb[2*HW + pixA];
    float gB0 = gb[pixB], gB1 = gb[HW + pixB], gB2 = gb[2*HW + pixB];

    __half2 h2a[16], h2b[16];
    #pragma unroll
    for (int k = 0; k < 16; k++) {
        float uA0 = fmaf(sw1[6*k],   gA0, fmaf(sw1[6*k+1], gA1, fmaf(sw1[6*k+2], gA2, sb1[2*k])));
        float uA1 = fmaf(sw1[6*k+3], gA0, fmaf(sw1[6*k+4], gA1, fmaf(sw1[6*k+5], gA2, sb1[2*k+1])));
        float uB0 = fmaf(sw1[6*k],   gB0, fmaf(sw1[6*k+1], gB1, fmaf(sw1[6*k+2], gB2, sb1[2*k])));
        float uB1 = fmaf(sw1[6*k+3], gB0, fmaf(sw1[6*k+4], gB1, fmaf(sw1[6*k+5], gB2, sb1[2*k+1])));
        h2a[k] = __floats2half2_rn(gelu_fast(uA0), gelu_fast(uA1));
        h2b[k] = __floats2half2_rn(gelu_fast(uB0), gelu_fast(uB1));
    }

    uint4* qb = g_qh + (size_t)(s*NB + b) * 4 * HW;
    #pragma unroll
    for (int g = 0; g < 4; g++) {
        float qA[8], qB[8];
        #pragma unroll
        for (int j = 0; j < 8; j++) {
            int row = 8*g + j;
            __half2 pa0 = __floats2half2_rn(0.f, 0.f), pa1 = pa0;
            __half2 pb0 = pa0, pb1 = pa0;
            #pragma unroll
            for (int k = 0; k < 16; k += 2) {          // weight LDS shared by both px
                __half2 w0 = sw2h[row*16 + k];
                __half2 w1 = sw2h[row*16 + k + 1];
                pa0 = __hfma2(w0, h2a[k],     pa0);
                pa1 = __hfma2(w1, h2a[k + 1], pa1);
                pb0 = __hfma2(w0, h2b[k],     pb0);
                pb1 = __hfma2(w1, h2b[k + 1], pb1);
            }
            float2 fa = __half22float2(__hadd2(pa0, pa1));
            float2 fb = __half22float2(__hadd2(pb0, pb1));
            qA[j] = sb2[row] + fa.x + fa.y;
            qB[j] = sb2[row] + fb.x + fb.y;
        }
        uint4 rA, rB;
        *reinterpret_cast<__half2*>(&rA.x) = __floats2half2_rn(qA[0], qA[1]);
        *reinterpret_cast<__half2*>(&rA.y) = __floats2half2_rn(qA[2], qA[3]);
        *reinterpret_cast<__half2*>(&rA.z) = __floats2half2_rn(qA[4], qA[5]);
        *reinterpret_cast<__half2*>(&rA.w) = __floats2half2_rn(qA[6], qA[7]);
        *reinterpret_cast<__half2*>(&rB.x) = __floats2half2_rn(qB[0], qB[1]);
        *reinterpret_cast<__half2*>(&rB.y) = __floats2half2_rn(qB[2], qB[3]);
        *reinterpret_cast<__half2*>(&rB.z) = __floats2half2_rn(qB[4], qB[5]);
        *reinterpret_cast<__half2*>(&rB.w) = __floats2half2_rn(qB[6], qB[7]);
        qb[(size_t)g * HW + pixA] = rA;
        qb[(size_t)g * HW + pixB] = rB;
    }
}

// ---- 32-ch fp16 dot: 4 independent HFMA2 chains (len 4) for ILP ----
__device__ __forceinline__ float qdot(const __half2* qc, const uint4& n0, const uint4& n1,
                                      const uint4& n2, const uint4& n3)
{
    const __half2* p0 = reinterpret_cast<const __half2*>(&n0);
    const __half2* p1 = reinterpret_cast<const __half2*>(&n1);
    const __half2* p2 = reinterpret_cast<const __half2*>(&n2);
    const __half2* p3 = reinterpret_cast<const __half2*>(&n3);
    __half2 a = __hmul2(qc[0], p0[0]);
    __half2 b = __hmul2(qc[1], p0[1]);
    __half2 c = __hmul2(qc[2], p0[2]);
    __half2 d = __hmul2(qc[3], p0[3]);
    a = __hfma2(qc[4],  p1[0], a);
    b = __hfma2(qc[5],  p1[1], b);
    c = __hfma2(qc[6],  p1[2], c);
    d = __hfma2(qc[7],  p1[3], d);
    a = __hfma2(qc[8],  p2[0], a);
    b = __hfma2(qc[9],  p2[1], b);
    c = __hfma2(qc[10], p2[2], c);
    d = __hfma2(qc[11], p2[3], d);
    a = __hfma2(qc[12], p3[0], a);
    b = __hfma2(qc[13], p3[1], b);
    c = __hfma2(qc[14], p3[2], c);
    d = __hfma2(qc[15], p3[3], d);
    float2 f = __half22float2(__hadd2(__hadd2(a, b), __hadd2(c, d)));
    return f.x + f.y;
}

// ------- fused JBU: smem halo tile, 2 rows/thread, online softmax + adaptive conv -------
__global__ void __launch_bounds__(128, 4) jbu_kernel(const float4* __restrict__ fin,
                                                     float4*       __restrict__ fout4,
                                                     float*        __restrict__ foutP,
                                                     const float* __restrict__ temps,
                                                     const float* __restrict__ sigmas,
                                                     int s)
{
    __shared__ uint4  sq[4][HALO_H][HALO_W];   // 34 KB
    __shared__ float4 sf[HALO_H][HALO_W];      // 8.5 KB

    int tx = threadIdx.x, ty = threadIdx.y;    // 32 x 4
    int tid = ty * 32 + tx;
    int wb = blockIdx.x * TILE_W;
    int hb = blockIdx.y * TILE_H;
    int b  = blockIdx.z;

    const uint4*  qb = g_qh + (size_t)(s*NB + b) * 4 * HW;
    const float4* fb = fin + (size_t)b * HW;

    // cooperative halo load (reflect at borders); coalesced along cols, full MLP
    #pragma unroll 2
    for (int i = tid; i < HALO_H * HALO_W; i += 128) {
        int row = i / HALO_W, col = i - row * HALO_W;
        int gy = refl(hb + row - 3);
        int gx = refl(wb + col - 3);
        size_t base = (size_t)gy * GW + gx;
        uint4 a0 = qb[base];
        uint4 a1 = qb[(size_t)HW + base];
        uint4 a2 = qb[(size_t)2*HW + base];
        uint4 a3 = qb[(size_t)3*HW + base];
        float4 fv = fb[base];
        sq[0][row][col] = a0;
        sq[1][row][col] = a1;
        sq[2][row][col] = a2;
        sq[3][row][col] = a3;
        sf[row][col] = fv;
    }
    __syncthreads();

    float t = __expf(temps[s]);
    t = fminf(fmaxf(t, 1e-4f), 1e4f);
    float sg = sigmas[s];
    float inv2s2 = 1.f / (2.f * sg * sg);

    // centers: pixels (hb + ty*2 + c, wb + tx), halo coords (ty*2+c+3, tx+3)
    __half2 qc[2][16];
    #pragma unroll
    for (int c = 0; c < 2; c++) {
        #pragma unroll
        for (int g = 0; g < 4; g++) {
            uint4 cv = sq[g][ty*2 + c + 3][tx + 3];
            const __half2* a = reinterpret_cast<const __half2*>(&cv);
            #pragma unroll
            for (int j = 0; j < 4; j++) qc[c][4*g+j] = a[j];
        }
    }

    float s0 = 0.f, o00 = 0.f, o01 = 0.f, o02 = 0.f;
    float s1 = 0.f, o10 = 0.f, o11 = 0.f, o12 = 0.f;

    #pragma unroll
    for (int r = 0; r < 8; r++) {               // halo rows ty*2 + r serve both centers
        #pragma unroll
        for (int ox = 0; ox < 7; ox++) {
            uint4 n0 = sq[0][ty*2 + r][tx + ox];
            uint4 n1 = sq[1][ty*2 + r][tx + ox];
            uint4 n2 = sq[2][ty*2 + r][tx + ox];
            uint4 n3 = sq[3][ty*2 + r][tx + ox];
            float4 v = sf[ty*2 + r][tx + ox];
            float dx = (ox - 3) * (1.f/3.f);
            float sx = dx * dx * inv2s2;
            if (r < 7) {                        // center row 0, oy = r-3
                float dyv = (r - 3) * (1.f/3.f);
                float d = qdot(qc[0], n0, n1, n2, n3);
                float e = __expf(fmaf(t, d, -fmaf(dyv, dyv * inv2s2, sx)));
                s0 += e;
                o00 = fmaf(e, v.x, o00);
                o01 = fmaf(e, v.y, o01);
                o02 = fmaf(e, v.z, o02);
            }
            if (r > 0) {                        // center row 1, oy = r-4
                float dyv = (r - 4) * (1.f/3.f);
                float d = qdot(qc[1], n0, n1, n2, n3);
                float e = __expf(fmaf(t, d, -fmaf(dyv, dyv * inv2s2, sx)));
                s1 += e;
                o10 = fmaf(e, v.x, o10);
                o11 = fmaf(e, v.y, o11);
                o12 = fmaf(e, v.z, o12);
            }
        }
    }
    float r0 = 1.f / s0, r1 = 1.f / s1;

    int pc0 = (hb + ty*2) * GW + wb + tx;
    if (foutP) {
        size_t o = (size_t)b * 3 * HW + pc0;
        foutP[o]             = o00 * r0;
        foutP[o + HW]        = o01 * r0;
        foutP[o + 2*HW]      = o02 * r0;
        foutP[o + GW]        = o10 * r1;
        foutP[o + HW + GW]   = o11 * r1;
        foutP[o + 2*HW + GW] = o12 * r1;
    } else {
        float4 a; a.x = o00 * r0; a.y = o01 * r0; a.z = o02 * r0; a.w = 0.f;
        float4 c; c.x = o10 * r1; c.y = o11 * r1; c.z = o12 * r1; c.w = 0.f;
        fout4[(size_t)b * HW + pc0]      = a;
        fout4[(size_t)b * HW + pc0 + GW] = c;
    }
}

// ---------------- launch ----------------
extern "C" void kernel_launch(void* const* d_in, const int* in_sizes, int n_in,
                              void* d_out, int out_size)
{
    const float* x      = (const float*)d_in[0];
    const float* gd     = (const float*)d_in[1];
    const float* lw     = (const float*)d_in[2];
    const float* lb     = (const float*)d_in[3];
    const float* w1s    = (const float*)d_in[4];
    const float* b1s    = (const float*)d_in[5];
    const float* w2s    = (const float*)d_in[6];
    const float* b2s    = (const float*)d_in[7];
    const float* temps  = (const float*)d_in[8];
    const float* sigmas = (const float*)d_in[9];
    float* out = (float*)d_out;

    float4 *f0 = nullptr, *f1 = nullptr;
    cudaGetSymbolAddress((void**)&f0, g_feat0);
    cudaGetSymbolAddress((void**)&f1, g_feat1);

    // lazily create side stream + events (no device mem involved)
    static cudaStream_t sQ = nullptr;
    static cudaEvent_t evFork = nullptr, evQ[4] = {nullptr,nullptr,nullptr,nullptr};
    if (!sQ) {
        cudaStreamCreateWithFlags(&sQ, cudaStreamNonBlocking);
        cudaEventCreateWithFlags(&evFork, cudaEventDisableTiming);
        for (int s = 0; s < 4; s++) cudaEventCreateWithFlags(&evQ[s], cudaEventDisableTiming);
    }

    dim3 qgrid(HW/512, NB);
    dim3 jgrid(GW/TILE_W, GH/TILE_H, NB);
    dim3 jblk(32, 4);

    float4* ins[4]  = { f0, f1, f0, f1 };
    float4* outs[4] = { f1, f0, f1, nullptr };

    // Submission order interleaves qproj/jbu so ncu (-s 5 -c 1) lands on a jbu launch.
    // Execution order is governed solely by streams + events.
    cudaEventRecord(evFork, 0);
    cudaStreamWaitEvent(sQ, evFork, 0);

    linear_kernel<<<972, 256>>>(x, lw, lb);                 // launch 1
    bicubic_kernel<<<dim3(HW/256, NB), 256>>>();            // launch 2
    for (int s = 0; s < 4; s++) {
        qproj_kernel<<<qgrid, 256, 0, sQ>>>(gd, w1s, b1s, w2s, b2s, s);  // launches 3,5,7,9
        cudaEventRecord(evQ[s], sQ);
        cudaStreamWaitEvent(0, evQ[s], 0);   // join: q[s] ready
        jbu_kernel<<<jgrid, jblk>>>(ins[s], outs[s], (s == 3) ? out : nullptr,
                                    temps, sigmas, s);                   // launches 4,6,8,10
    }
}